// round 1
// baseline (speedup 1.0000x reference)
#include <cuda_runtime.h>
#include <math.h>

#define TGT 2048
#define BSZ 2
#define EMB 1024
#define NH 16
#define HD 64
#define ROWS (TGT*BSZ)              // 4096
#define BH (BSZ*NH)                 // 32
#define ATTN_N (ROWS*EMB)           // 4194304
#define W_ELEMS (134217728LL)       // 32*2048*2048
#define NEGMAX (-3.4028234663852886e38f)

// ---------------- scratch (static device memory; no allocations) -------------
__device__ float g_q[ROWS*EMB];
__device__ float g_k[ROWS*EMB];
__device__ float g_v[ROWS*EMB];
__device__ float g_ctx[ROWS*EMB];
__device__ float g_wfallback[134217728];   // used only if d_out lacks the weights region
__device__ unsigned char g_mask[BSZ*TGT];

// ---------------- mask dtype auto-detect + normalize -------------------------
__global__ void mask_prep(const void* m) {
    __shared__ int mode;
    int tid = threadIdx.x;
    if (tid == 0) {
        const int* mi = (const int*)m;
        int ok_i = 1;
        for (int i = 0; i < 1024; i++) { int v = mi[i]; if (v != 0 && v != 1) { ok_i = 0; break; } }
        if (ok_i) mode = 0;
        else {
            const float* mf = (const float*)m;
            int ok_f = 1;
            for (int i = 0; i < 1024; i++) { float v = mf[i]; if (v != 0.0f && v != 1.0f) { ok_f = 0; break; } }
            mode = ok_f ? 1 : 2;
        }
    }
    __syncthreads();
    int md = mode;
    for (int i = tid; i < BSZ*TGT; i += blockDim.x) {
        bool b;
        if (md == 0)      b = ((const int*)m)[i] != 0;
        else if (md == 1) b = ((const float*)m)[i] != 0.0f;
        else              b = ((const unsigned char*)m)[i] != 0;
        g_mask[i] = b ? 1 : 0;
    }
}

// ---------------- generic NT GEMM:  C[M,N] = (A[M,K] @ B[N,K]^T + bias)*scale --
__global__ __launch_bounds__(256) void gemm_nt(
    const float* __restrict__ A, const float* __restrict__ B,
    const float* __restrict__ bias, float* __restrict__ C,
    int M, int N, int K, float scale)
{
    __shared__ float As[16][128];
    __shared__ float Bs[16][128];
    int tid = threadIdx.x;
    int tx = tid & 15, ty = tid >> 4;
    int m0 = blockIdx.y * 128, n0 = blockIdx.x * 128;

    float acc[8][8];
#pragma unroll
    for (int i = 0; i < 8; i++)
#pragma unroll
        for (int j = 0; j < 8; j++) acc[i][j] = 0.f;

    for (int kt = 0; kt < K; kt += 16) {
#pragma unroll
        for (int i = 0; i < 2; i++) {
            int t4 = tid * 2 + i;
            int r = t4 >> 2, c = (t4 & 3) * 4;
            float4 va = *(const float4*)(A + (long long)(m0 + r) * K + kt + c);
            As[c + 0][r] = va.x; As[c + 1][r] = va.y; As[c + 2][r] = va.z; As[c + 3][r] = va.w;
            float4 vb = *(const float4*)(B + (long long)(n0 + r) * K + kt + c);
            Bs[c + 0][r] = vb.x; Bs[c + 1][r] = vb.y; Bs[c + 2][r] = vb.z; Bs[c + 3][r] = vb.w;
        }
        __syncthreads();
#pragma unroll
        for (int k = 0; k < 16; k++) {
            float a[8], b[8];
#pragma unroll
            for (int i = 0; i < 8; i++) a[i] = As[k][ty * 8 + i];
#pragma unroll
            for (int j = 0; j < 8; j++) b[j] = Bs[k][tx * 8 + j];
#pragma unroll
            for (int i = 0; i < 8; i++)
#pragma unroll
                for (int j = 0; j < 8; j++) acc[i][j] += a[i] * b[j];
        }
        __syncthreads();
    }
#pragma unroll
    for (int i = 0; i < 8; i++) {
        int r = m0 + ty * 8 + i;
#pragma unroll
        for (int j = 0; j < 8; j++) {
            int cidx = n0 + tx * 8 + j;
            float bb = bias ? bias[cidx] : 0.f;
            C[(long long)r * N + cidx] = (acc[i][j] + bb) * scale;
        }
    }
}

// ---------------- scores: S[bh,128q,128k] tiles = Q@K^T with padding mask ----
__global__ __launch_bounds__(256) void scores_kernel(
    const float* __restrict__ q, const float* __restrict__ k, float* __restrict__ W)
{
    __shared__ float Qs[16][128];
    __shared__ float Ks[16][128];
    int bh = blockIdx.z;
    int b = bh >> 4;
    int base = b * EMB + (bh & 15) * HD;        // column offset into [t, b*1024 + h*64 + d]
    int m0 = blockIdx.y * 128, n0 = blockIdx.x * 128;
    int tid = threadIdx.x;
    int tx = tid & 15, ty = tid >> 4;

    float acc[8][8];
#pragma unroll
    for (int i = 0; i < 8; i++)
#pragma unroll
        for (int j = 0; j < 8; j++) acc[i][j] = 0.f;

    for (int kt = 0; kt < HD; kt += 16) {
#pragma unroll
        for (int i = 0; i < 2; i++) {
            int t4 = tid * 2 + i;
            int r = t4 >> 2, c = (t4 & 3) * 4;
            float4 va = *(const float4*)(q + (long long)(m0 + r) * (BSZ*EMB) + base + kt + c);
            Qs[c + 0][r] = va.x; Qs[c + 1][r] = va.y; Qs[c + 2][r] = va.z; Qs[c + 3][r] = va.w;
            float4 vb = *(const float4*)(k + (long long)(n0 + r) * (BSZ*EMB) + base + kt + c);
            Ks[c + 0][r] = vb.x; Ks[c + 1][r] = vb.y; Ks[c + 2][r] = vb.z; Ks[c + 3][r] = vb.w;
        }
        __syncthreads();
#pragma unroll
        for (int k2 = 0; k2 < 16; k2++) {
            float a[8], bb[8];
#pragma unroll
            for (int i = 0; i < 8; i++) a[i] = Qs[k2][ty * 8 + i];
#pragma unroll
            for (int j = 0; j < 8; j++) bb[j] = Ks[k2][tx * 8 + j];
#pragma unroll
            for (int i = 0; i < 8; i++)
#pragma unroll
                for (int j = 0; j < 8; j++) acc[i][j] += a[i] * bb[j];
        }
        __syncthreads();
    }

    long long wbase = (long long)bh * TGT * TGT;
#pragma unroll
    for (int i = 0; i < 8; i++) {
        int r = m0 + ty * 8 + i;
#pragma unroll
        for (int j = 0; j < 8; j++) {
            int n = n0 + tx * 8 + j;
            float v = acc[i][j];
            if (g_mask[b * TGT + n]) v = NEGMAX;
            W[wbase + (long long)r * TGT + n] = v;
        }
    }
}

// ---------------- row softmax over 2048, in place ----------------------------
__global__ __launch_bounds__(256) void softmax_rows(float* __restrict__ W)
{
    long long row = blockIdx.x;
    float* p = W + row * TGT;
    int tid = threadIdx.x;
    __shared__ float red[32];

    float v[8];
#pragma unroll
    for (int i = 0; i < 8; i++) v[i] = p[tid + i * 256];

    float m = -INFINITY;
#pragma unroll
    for (int i = 0; i < 8; i++) m = fmaxf(m, v[i]);
#pragma unroll
    for (int o = 16; o > 0; o >>= 1) m = fmaxf(m, __shfl_xor_sync(0xffffffffu, m, o));
    if ((tid & 31) == 0) red[tid >> 5] = m;
    __syncthreads();
    if (tid < 32) {
        float x = (tid < 8) ? red[tid] : -INFINITY;
#pragma unroll
        for (int o = 4; o > 0; o >>= 1) x = fmaxf(x, __shfl_xor_sync(0xffffffffu, x, o));
        if (tid == 0) red[0] = x;
    }
    __syncthreads();
    m = red[0];
    __syncthreads();

    float s = 0.f;
#pragma unroll
    for (int i = 0; i < 8; i++) { v[i] = __expf(v[i] - m); s += v[i]; }
#pragma unroll
    for (int o = 16; o > 0; o >>= 1) s += __shfl_xor_sync(0xffffffffu, s, o);
    if ((tid & 31) == 0) red[tid >> 5] = s;
    __syncthreads();
    if (tid < 32) {
        float x = (tid < 8) ? red[tid] : 0.f;
#pragma unroll
        for (int o = 4; o > 0; o >>= 1) x += __shfl_xor_sync(0xffffffffu, x, o);
        if (tid == 0) red[0] = x;
    }
    __syncthreads();
    float inv = 1.0f / red[0];
#pragma unroll
    for (int i = 0; i < 8; i++) p[tid + i * 256] = v[i] * inv;
}

// ---------------- AV: ctx = P @ V, written in (t*bsz+b, head*64+d) layout -----
__global__ __launch_bounds__(256) void av_kernel(
    const float* __restrict__ W, const float* __restrict__ v, float* __restrict__ ctx)
{
    __shared__ float Ps[16][128];
    __shared__ float Vs[16][64];
    int bh = blockIdx.z;
    int b = bh >> 4;
    int base = b * EMB + (bh & 15) * HD;
    int m0 = blockIdx.y * 128;
    const float* P = W + (long long)bh * TGT * TGT;
    int tid = threadIdx.x;
    int tx = tid & 15, ty = tid >> 4;

    float acc[8][4];
#pragma unroll
    for (int i = 0; i < 8; i++)
#pragma unroll
        for (int j = 0; j < 4; j++) acc[i][j] = 0.f;

    for (int kt = 0; kt < TGT; kt += 16) {
#pragma unroll
        for (int i = 0; i < 2; i++) {
            int t4 = tid * 2 + i;
            int r = t4 >> 2, c = (t4 & 3) * 4;
            float4 pv = *(const float4*)(P + (long long)(m0 + r) * TGT + kt + c);
            Ps[c + 0][r] = pv.x; Ps[c + 1][r] = pv.y; Ps[c + 2][r] = pv.z; Ps[c + 3][r] = pv.w;
        }
        {
            int r2 = tid >> 4, d = (tid & 15) * 4;
            float4 vv = *(const float4*)(v + (long long)(kt + r2) * (BSZ*EMB) + base + d);
            Vs[r2][d + 0] = vv.x; Vs[r2][d + 1] = vv.y; Vs[r2][d + 2] = vv.z; Vs[r2][d + 3] = vv.w;
        }
        __syncthreads();
#pragma unroll
        for (int k2 = 0; k2 < 16; k2++) {
            float a[8], bv[4];
#pragma unroll
            for (int i = 0; i < 8; i++) a[i] = Ps[k2][ty * 8 + i];
#pragma unroll
            for (int j = 0; j < 4; j++) bv[j] = Vs[k2][tx * 4 + j];
#pragma unroll
            for (int i = 0; i < 8; i++)
#pragma unroll
                for (int j = 0; j < 4; j++) acc[i][j] += a[i] * bv[j];
        }
        __syncthreads();
    }
#pragma unroll
    for (int i = 0; i < 8; i++) {
        int t = m0 + ty * 8 + i;
#pragma unroll
        for (int j = 0; j < 4; j++) {
            int d = tx * 4 + j;
            ctx[(long long)(t * BSZ + b) * EMB + (bh & 15) * HD + d] = acc[i][j];
        }
    }
}

// ---------------- launch -----------------------------------------------------
extern "C" void kernel_launch(void* const* d_in, const int* in_sizes, int n_in,
                              void* d_out, int out_size)
{
    const float* query = (const float*)d_in[0];
    const void*  maskp = d_in[1];
    const float* qw = (const float*)d_in[2];
    const float* qb = (const float*)d_in[3];
    const float* kw = (const float*)d_in[4];
    const float* kb = (const float*)d_in[5];
    const float* vw = (const float*)d_in[6];
    const float* vb = (const float*)d_in[7];
    const float* ow = (const float*)d_in[8];
    const float* ob = (const float*)d_in[9];
    float* out = (float*)d_out;

    float *pq, *pk, *pv, *pctx, *pwf;
    cudaGetSymbolAddress((void**)&pq,   g_q);
    cudaGetSymbolAddress((void**)&pk,   g_k);
    cudaGetSymbolAddress((void**)&pv,   g_v);
    cudaGetSymbolAddress((void**)&pctx, g_ctx);
    cudaGetSymbolAddress((void**)&pwf,  g_wfallback);

    // where do the attention weights live?
    float* W = ((long long)out_size >= (long long)ATTN_N + W_ELEMS) ? (out + ATTN_N) : pwf;

    mask_prep<<<1, 256>>>(maskp);

    dim3 gproj(EMB / 128, ROWS / 128);         // (8, 32)
    gemm_nt<<<gproj, 256>>>(query, qw, qb, pq, ROWS, EMB, EMB, 0.125f);
    gemm_nt<<<gproj, 256>>>(query, kw, kb, pk, ROWS, EMB, EMB, 1.0f);
    gemm_nt<<<gproj, 256>>>(query, vw, vb, pv, ROWS, EMB, EMB, 1.0f);

    scores_kernel<<<dim3(TGT / 128, TGT / 128, BH), 256>>>(pq, pk, W);

    softmax_rows<<<BH * TGT, 256>>>(W);

    av_kernel<<<dim3(1, TGT / 128, BH), 256>>>(W, pv, pctx);

    gemm_nt<<<gproj, 256>>>(pctx, ow, ob, out, ROWS, EMB, EMB, 1.0f);
}

// round 2
// speedup vs baseline: 1.0521x; 1.0521x over previous
#include <cuda_runtime.h>
#include <math.h>

#define TGT 2048
#define BSZ 2
#define EMB 1024
#define NH 16
#define HD 64
#define ROWS (TGT*BSZ)              // 4096
#define BH (BSZ*NH)                 // 32
#define ATTN_N (ROWS*EMB)           // 4194304
#define W_ELEMS (134217728LL)       // 32*2048*2048
#define NEGMAX (-3.4028234663852886e38f)
#define NTILE 16                    // 2048/128 key tiles

// ---------------- scratch (static device memory; no allocations) -------------
__device__ float g_q[ROWS*EMB];
__device__ float g_k[ROWS*EMB];
__device__ float g_v[ROWS*EMB];
__device__ float g_ctx[ROWS*EMB];
__device__ float g_wfallback[134217728];   // used only if d_out lacks the weights region
__device__ unsigned char g_mask[BSZ*TGT];
__device__ float g_tmax[BH*NTILE*TGT];
__device__ float g_tsum[BH*NTILE*TGT];
__device__ float g_rmax[BH*TGT];
__device__ float g_rinv[BH*TGT];

// ---------------- mask dtype auto-detect + normalize -------------------------
__global__ void mask_prep(const void* m) {
    __shared__ int mode;
    int tid = threadIdx.x;
    if (tid == 0) {
        const int* mi = (const int*)m;
        int ok_i = 1;
        for (int i = 0; i < 1024; i++) { int v = mi[i]; if (v != 0 && v != 1) { ok_i = 0; break; } }
        if (ok_i) mode = 0;
        else {
            const float* mf = (const float*)m;
            int ok_f = 1;
            for (int i = 0; i < 1024; i++) { float v = mf[i]; if (v != 0.0f && v != 1.0f) { ok_f = 0; break; } }
            mode = ok_f ? 1 : 2;
        }
    }
    __syncthreads();
    int md = mode;
    for (int i = tid; i < BSZ*TGT; i += blockDim.x) {
        bool b;
        if (md == 0)      b = ((const int*)m)[i] != 0;
        else if (md == 1) b = ((const float*)m)[i] != 0.0f;
        else              b = ((const unsigned char*)m)[i] != 0;
        g_mask[i] = b ? 1 : 0;
    }
}

// ------- double-buffered NT GEMM: C[M,N] = (A[M,K] @ B[N,K]^T + bias)*scale ---
__global__ __launch_bounds__(256, 2) void gemm_nt(
    const float* __restrict__ A, const float* __restrict__ B,
    const float* __restrict__ bias, float* __restrict__ C,
    int M, int N, int K, float scale)
{
    __shared__ float As[2][16][128];
    __shared__ float Bs[2][16][128];
    int tid = threadIdx.x;
    int tx = tid & 15, ty = tid >> 4;
    int m0 = blockIdx.y * 128, n0 = blockIdx.x * 128;
    const float* Ab = A + (long long)m0 * K;
    const float* Bb = B + (long long)n0 * K;

    int t4a = tid * 2, t4b = tid * 2 + 1;
    int ra = t4a >> 2, ca = (t4a & 3) * 4;
    int rb = t4b >> 2, cb = (t4b & 3) * 4;

    float acc[8][8];
#pragma unroll
    for (int i = 0; i < 8; i++)
#pragma unroll
        for (int j = 0; j < 8; j++) acc[i][j] = 0.f;

    // prologue: stage kt=0
    float4 va0 = *(const float4*)(Ab + (long long)ra * K + ca);
    float4 va1 = *(const float4*)(Ab + (long long)rb * K + cb);
    float4 vb0 = *(const float4*)(Bb + (long long)ra * K + ca);
    float4 vb1 = *(const float4*)(Bb + (long long)rb * K + cb);
    As[0][ca+0][ra]=va0.x; As[0][ca+1][ra]=va0.y; As[0][ca+2][ra]=va0.z; As[0][ca+3][ra]=va0.w;
    As[0][cb+0][rb]=va1.x; As[0][cb+1][rb]=va1.y; As[0][cb+2][rb]=va1.z; As[0][cb+3][rb]=va1.w;
    Bs[0][ca+0][ra]=vb0.x; Bs[0][ca+1][ra]=vb0.y; Bs[0][ca+2][ra]=vb0.z; Bs[0][ca+3][ra]=vb0.w;
    Bs[0][cb+0][rb]=vb1.x; Bs[0][cb+1][rb]=vb1.y; Bs[0][cb+2][rb]=vb1.z; Bs[0][cb+3][rb]=vb1.w;
    __syncthreads();

    int nk = K >> 4;
    for (int t = 0; t < nk; t++) {
        int buf = t & 1;
        bool more = (t + 1 < nk);
        if (more) {
            int kt = (t + 1) << 4;
            va0 = *(const float4*)(Ab + (long long)ra * K + kt + ca);
            va1 = *(const float4*)(Ab + (long long)rb * K + kt + cb);
            vb0 = *(const float4*)(Bb + (long long)ra * K + kt + ca);
            vb1 = *(const float4*)(Bb + (long long)rb * K + kt + cb);
        }
#pragma unroll
        for (int k = 0; k < 16; k++) {
            float4 a0 = *(const float4*)&As[buf][k][ty * 8];
            float4 a1 = *(const float4*)&As[buf][k][ty * 8 + 4];
            float4 b0 = *(const float4*)&Bs[buf][k][tx * 8];
            float4 b1 = *(const float4*)&Bs[buf][k][tx * 8 + 4];
            float a[8] = {a0.x,a0.y,a0.z,a0.w,a1.x,a1.y,a1.z,a1.w};
            float b[8] = {b0.x,b0.y,b0.z,b0.w,b1.x,b1.y,b1.z,b1.w};
#pragma unroll
            for (int i = 0; i < 8; i++)
#pragma unroll
                for (int j = 0; j < 8; j++) acc[i][j] += a[i] * b[j];
        }
        if (more) {
            int nb = buf ^ 1;
            As[nb][ca+0][ra]=va0.x; As[nb][ca+1][ra]=va0.y; As[nb][ca+2][ra]=va0.z; As[nb][ca+3][ra]=va0.w;
            As[nb][cb+0][rb]=va1.x; As[nb][cb+1][rb]=va1.y; As[nb][cb+2][rb]=va1.z; As[nb][cb+3][rb]=va1.w;
            Bs[nb][ca+0][ra]=vb0.x; Bs[nb][ca+1][ra]=vb0.y; Bs[nb][ca+2][ra]=vb0.z; Bs[nb][ca+3][ra]=vb0.w;
            Bs[nb][cb+0][rb]=vb1.x; Bs[nb][cb+1][rb]=vb1.y; Bs[nb][cb+2][rb]=vb1.z; Bs[nb][cb+3][rb]=vb1.w;
        }
        __syncthreads();
    }
#pragma unroll
    for (int i = 0; i < 8; i++) {
        int r = m0 + ty * 8 + i;
#pragma unroll
        for (int j = 0; j < 8; j++) {
            int cidx = n0 + tx * 8 + j;
            float bb = bias ? bias[cidx] : 0.f;
            C[(long long)r * N + cidx] = (acc[i][j] + bb) * scale;
        }
    }
}

// ------- scores: raw masked S tiles + per-tile row (max, sumexp) stats --------
__global__ __launch_bounds__(256) void scores_kernel(
    const float* __restrict__ q, const float* __restrict__ k, float* __restrict__ W)
{
    __shared__ float Qs[16][128];
    __shared__ float Ks[16][128];
    int bh = blockIdx.z;
    int b = bh >> 4;
    int base = b * EMB + (bh & 15) * HD;
    int m0 = blockIdx.y * 128, n0 = blockIdx.x * 128;
    int tile = blockIdx.x;
    int tid = threadIdx.x;
    int tx = tid & 15, ty = tid >> 4;

    float acc[8][8];
#pragma unroll
    for (int i = 0; i < 8; i++)
#pragma unroll
        for (int j = 0; j < 8; j++) acc[i][j] = 0.f;

    for (int kt = 0; kt < HD; kt += 16) {
#pragma unroll
        for (int i = 0; i < 2; i++) {
            int t4 = tid * 2 + i;
            int r = t4 >> 2, c = (t4 & 3) * 4;
            float4 va = *(const float4*)(q + (long long)(m0 + r) * (BSZ*EMB) + base + kt + c);
            Qs[c + 0][r] = va.x; Qs[c + 1][r] = va.y; Qs[c + 2][r] = va.z; Qs[c + 3][r] = va.w;
            float4 vb = *(const float4*)(k + (long long)(n0 + r) * (BSZ*EMB) + base + kt + c);
            Ks[c + 0][r] = vb.x; Ks[c + 1][r] = vb.y; Ks[c + 2][r] = vb.z; Ks[c + 3][r] = vb.w;
        }
        __syncthreads();
#pragma unroll
        for (int k2 = 0; k2 < 16; k2++) {
            float a[8], bb[8];
#pragma unroll
            for (int i = 0; i < 8; i++) a[i] = Qs[k2][ty * 8 + i];
#pragma unroll
            for (int j = 0; j < 8; j++) bb[j] = Ks[k2][tx * 8 + j];
#pragma unroll
            for (int i = 0; i < 8; i++)
#pragma unroll
                for (int j = 0; j < 8; j++) acc[i][j] += a[i] * bb[j];
        }
        __syncthreads();
    }

    // mask in registers
    unsigned char mk[8];
#pragma unroll
    for (int j = 0; j < 8; j++) mk[j] = g_mask[b * TGT + n0 + tx * 8 + j];

    long long wbase = (long long)bh * TGT * TGT;
#pragma unroll
    for (int i = 0; i < 8; i++) {
        int r = m0 + ty * 8 + i;
        float v[8];
        float mx = -INFINITY;
#pragma unroll
        for (int j = 0; j < 8; j++) {
            float x = acc[i][j];
            if (mk[j]) x = NEGMAX;
            v[j] = x;
            mx = fmaxf(mx, x);
        }
        // write raw masked scores
        float4* wp = (float4*)(W + wbase + (long long)r * TGT + n0 + tx * 8);
        wp[0] = make_float4(v[0], v[1], v[2], v[3]);
        wp[1] = make_float4(v[4], v[5], v[6], v[7]);
        // row max across tx group (16 lanes, same warp)
#pragma unroll
        for (int o = 8; o > 0; o >>= 1) mx = fmaxf(mx, __shfl_xor_sync(0xffffffffu, mx, o, 16));
        float se = 0.f;
#pragma unroll
        for (int j = 0; j < 8; j++) se += __expf(v[j] - mx);
#pragma unroll
        for (int o = 8; o > 0; o >>= 1) se += __shfl_xor_sync(0xffffffffu, se, o, 16);
        if (tx == 0) {
            int sidx = (bh * NTILE + tile) * TGT + r;
            g_tmax[sidx] = mx;
            g_tsum[sidx] = se;
        }
    }
}

// ------- combine per-tile stats into per-row (max, 1/sum) ---------------------
__global__ __launch_bounds__(256) void stats_combine()
{
    int idx = blockIdx.x * 256 + threadIdx.x;   // 0 .. BH*TGT-1
    int bh = idx >> 11, row = idx & 2047;
    float gm = -INFINITY;
#pragma unroll
    for (int t = 0; t < NTILE; t++)
        gm = fmaxf(gm, g_tmax[(bh * NTILE + t) * TGT + row]);
    float s = 0.f;
#pragma unroll
    for (int t = 0; t < NTILE; t++)
        s += g_tsum[(bh * NTILE + t) * TGT + row] * __expf(g_tmax[(bh * NTILE + t) * TGT + row] - gm);
    g_rmax[idx] = gm;
    g_rinv[idx] = 1.0f / s;
}

// ------- AV with fused normalization: normalizes S in place (-> attn_weights),
//         computes ctx = P @ V ----------------------------------------------
__global__ __launch_bounds__(256) void av_norm_kernel(
    float* __restrict__ W, const float* __restrict__ v, float* __restrict__ ctx)
{
    __shared__ float Ps[64][128];   // [key][row]
    __shared__ float Vs[64][64];    // [key][d]
    int bh = blockIdx.y;
    int b = bh >> 4;
    int base = b * EMB + (bh & 15) * HD;
    int m0 = blockIdx.x * 128;
    float* P = W + (long long)bh * TGT * TGT;
    int tid = threadIdx.x;
    int tx = tid & 15, ty = tid >> 4;

    // each loader thread owns a single row of S for the whole kernel
    int myrow = tid >> 1;                   // 0..127
    int mycol0 = (tid & 1) * 32;            // col offset within 64-wide chunk
    float myrm  = g_rmax[bh * TGT + m0 + myrow];
    float myri  = g_rinv[bh * TGT + m0 + myrow];

    float acc[8][4];
#pragma unroll
    for (int i = 0; i < 8; i++)
#pragma unroll
        for (int j = 0; j < 4; j++) acc[i][j] = 0.f;

    for (int kt = 0; kt < TGT; kt += 64) {
        // load S chunk rows, normalize, write back, transpose into smem
        float* srow = P + (long long)(m0 + myrow) * TGT + kt + mycol0;
#pragma unroll
        for (int l = 0; l < 8; l++) {
            float4 s4 = *(float4*)(srow + l * 4);
            float4 p4;
            p4.x = __expf(s4.x - myrm) * myri;
            p4.y = __expf(s4.y - myrm) * myri;
            p4.z = __expf(s4.z - myrm) * myri;
            p4.w = __expf(s4.w - myrm) * myri;
            *(float4*)(srow + l * 4) = p4;
            int c = mycol0 + l * 4;
            Ps[c + 0][myrow] = p4.x;
            Ps[c + 1][myrow] = p4.y;
            Ps[c + 2][myrow] = p4.z;
            Ps[c + 3][myrow] = p4.w;
        }
        // load V chunk: 64 keys x 64 d
#pragma unroll
        for (int l = 0; l < 4; l++) {
            int e = tid * 4 + l;
            int key = e >> 4, d = (e & 15) * 4;
            float4 v4 = *(const float4*)(v + (long long)(kt + key) * (BSZ*EMB) + base + d);
            *(float4*)&Vs[key][d] = v4;
        }
        __syncthreads();
#pragma unroll 4
        for (int k2 = 0; k2 < 64; k2++) {
            float4 a0 = *(const float4*)&Ps[k2][ty * 8];
            float4 a1 = *(const float4*)&Ps[k2][ty * 8 + 4];
            float4 bv = *(const float4*)&Vs[k2][tx * 4];
            float a[8] = {a0.x,a0.y,a0.z,a0.w,a1.x,a1.y,a1.z,a1.w};
            float bb[4] = {bv.x,bv.y,bv.z,bv.w};
#pragma unroll
            for (int i = 0; i < 8; i++)
#pragma unroll
                for (int j = 0; j < 4; j++) acc[i][j] += a[i] * bb[j];
        }
        __syncthreads();
    }
#pragma unroll
    for (int i = 0; i < 8; i++) {
        int t = m0 + ty * 8 + i;
#pragma unroll
        for (int j = 0; j < 4; j++) {
            int d = tx * 4 + j;
            ctx[(long long)(t * BSZ + b) * EMB + (bh & 15) * HD + d] = acc[i][j];
        }
    }
}

// ---------------- launch -----------------------------------------------------
extern "C" void kernel_launch(void* const* d_in, const int* in_sizes, int n_in,
                              void* d_out, int out_size)
{
    const float* query = (const float*)d_in[0];
    const void*  maskp = d_in[1];
    const float* qw = (const float*)d_in[2];
    const float* qb = (const float*)d_in[3];
    const float* kw = (const float*)d_in[4];
    const float* kb = (const float*)d_in[5];
    const float* vw = (const float*)d_in[6];
    const float* vb = (const float*)d_in[7];
    const float* ow = (const float*)d_in[8];
    const float* ob = (const float*)d_in[9];
    float* out = (float*)d_out;

    float *pq, *pk, *pv, *pctx, *pwf;
    cudaGetSymbolAddress((void**)&pq,   g_q);
    cudaGetSymbolAddress((void**)&pk,   g_k);
    cudaGetSymbolAddress((void**)&pv,   g_v);
    cudaGetSymbolAddress((void**)&pctx, g_ctx);
    cudaGetSymbolAddress((void**)&pwf,  g_wfallback);

    float* W = ((long long)out_size >= (long long)ATTN_N + W_ELEMS) ? (out + ATTN_N) : pwf;

    mask_prep<<<1, 256>>>(maskp);

    dim3 gproj(EMB / 128, ROWS / 128);         // (8, 32)
    gemm_nt<<<gproj, 256>>>(query, qw, qb, pq, ROWS, EMB, EMB, 0.125f);
    gemm_nt<<<gproj, 256>>>(query, kw, kb, pk, ROWS, EMB, EMB, 1.0f);
    gemm_nt<<<gproj, 256>>>(query, vw, vb, pv, ROWS, EMB, EMB, 1.0f);

    scores_kernel<<<dim3(TGT / 128, TGT / 128, BH), 256>>>(pq, pk, W);

    stats_combine<<<BH * TGT / 256, 256>>>();

    av_norm_kernel<<<dim3(TGT / 128, BH), 256>>>(W, pv, pctx);

    gemm_nt<<<gproj, 256>>>(pctx, ow, ob, out, ROWS, EMB, EMB, 1.0f);
}

// round 4
// speedup vs baseline: 1.3683x; 1.3006x over previous
#include <cuda_runtime.h>
#include <cuda_bf16.h>
#include <math.h>
#include <stdint.h>

#define TGT 2048
#define BSZ 2
#define EMB 1024
#define NH 16
#define HD 64
#define ROWS (TGT*BSZ)              // 4096
#define BH (BSZ*NH)                 // 32
#define ATTN_N (ROWS*EMB)           // 4194304
#define W_ELEMS (134217728LL)       // 32*2048*2048
#define NEGMAX (-3.4028234663852886e38f)
#define NTILE 16                    // 2048/128 key tiles

// ---------------- scratch (static device memory; no allocations) -------------
__device__ float g_q[ROWS*EMB];
__device__ float g_k[ROWS*EMB];
__device__ float g_v[ROWS*EMB];
__device__ float g_ctx[ROWS*EMB];
__device__ float g_wfallback[134217728];
__device__ unsigned char g_mask[BSZ*TGT];
__device__ float g_tmax[BH*NTILE*TGT];
__device__ float g_tsum[BH*NTILE*TGT];
__device__ float g_rmax[BH*TGT];
__device__ float g_rinv[BH*TGT];

// split-bf16 operands
__device__ __nv_bfloat16 g_ah[ROWS*EMB], g_al[ROWS*EMB];          // query hi/lo
__device__ __nv_bfloat16 g_ch[ROWS*EMB], g_cl[ROWS*EMB];          // ctx hi/lo
__device__ __nv_bfloat16 g_qwh[EMB*EMB], g_qwl[EMB*EMB];
__device__ __nv_bfloat16 g_kwh[EMB*EMB], g_kwl[EMB*EMB];
__device__ __nv_bfloat16 g_vwh[EMB*EMB], g_vwl[EMB*EMB];
__device__ __nv_bfloat16 g_owh[EMB*EMB], g_owl[EMB*EMB];

// ---------------- helpers ----------------------------------------------------
__device__ __forceinline__ uint32_t smem_u32(const void* p) {
    uint32_t a;
    asm("{ .reg .u64 t; cvta.to.shared.u64 t, %1; cvt.u32.u64 %0, t; }" : "=r"(a) : "l"(p));
    return a;
}
__device__ __forceinline__ void ldmx4(uint32_t& r0, uint32_t& r1, uint32_t& r2, uint32_t& r3, uint32_t addr) {
    asm volatile("ldmatrix.sync.aligned.m8n8.x4.shared.b16 {%0,%1,%2,%3}, [%4];"
                 : "=r"(r0), "=r"(r1), "=r"(r2), "=r"(r3) : "r"(addr));
}
__device__ __forceinline__ void mma_bf16(float* d, const uint32_t* a, const uint32_t* b) {
    asm volatile("mma.sync.aligned.m16n8k16.row.col.f32.bf16.bf16.f32 "
                 "{%0,%1,%2,%3}, {%4,%5,%6,%7}, {%8,%9}, {%0,%1,%2,%3};"
                 : "+f"(d[0]), "+f"(d[1]), "+f"(d[2]), "+f"(d[3])
                 : "r"(a[0]), "r"(a[1]), "r"(a[2]), "r"(a[3]), "r"(b[0]), "r"(b[1]));
}

// ---------------- fp32 -> (hi, lo) bf16 split --------------------------------
__global__ __launch_bounds__(256) void split_kernel(const float* __restrict__ in,
                                                    __nv_bfloat16* __restrict__ hi,
                                                    __nv_bfloat16* __restrict__ lo, int n)
{
    int i = (blockIdx.x * 256 + threadIdx.x) * 4;
    if (i >= n) return;
    float4 x = *(const float4*)(in + i);
    __nv_bfloat16 h0 = __float2bfloat16_rn(x.x), h1 = __float2bfloat16_rn(x.y);
    __nv_bfloat16 h2 = __float2bfloat16_rn(x.z), h3 = __float2bfloat16_rn(x.w);
    __nv_bfloat162 hh0, hh1, ll0, ll1;
    hh0.x = h0; hh0.y = h1; hh1.x = h2; hh1.y = h3;
    ll0.x = __float2bfloat16_rn(x.x - __bfloat162float(h0));
    ll0.y = __float2bfloat16_rn(x.y - __bfloat162float(h1));
    ll1.x = __float2bfloat16_rn(x.z - __bfloat162float(h2));
    ll1.y = __float2bfloat16_rn(x.w - __bfloat162float(h3));
    *(__nv_bfloat162*)(hi + i) = hh0; *(__nv_bfloat162*)(hi + i + 2) = hh1;
    *(__nv_bfloat162*)(lo + i) = ll0; *(__nv_bfloat162*)(lo + i + 2) = ll1;
}

// ---------------- split-bf16 HMMA NT GEMM ------------------------------------
// C[M,1024] = (Ah+Al)[M,1024] @ (Bh+Bl)[1024,1024]^T, +bias, *scale
// 128x128 CTA tile, 8 warps as 2(m) x 4(n), warp tile 64x32. K chunk 32.
#define KD 1024
#define SSTR 40   // smem row stride in halves (padding -> conflict-free ldmatrix)

__global__ __launch_bounds__(256, 2) void hgemm(
    const __nv_bfloat16* __restrict__ Ah, const __nv_bfloat16* __restrict__ Al,
    const __nv_bfloat16* __restrict__ Bh, const __nv_bfloat16* __restrict__ Bl,
    const float* __restrict__ bias, float* __restrict__ C, float scale)
{
    __shared__ __align__(16) __nv_bfloat16 sA[2][128 * SSTR];  // [hi/lo]
    __shared__ __align__(16) __nv_bfloat16 sB[2][128 * SSTR];

    int tid = threadIdx.x;
    int warp = tid >> 5, lane = tid & 31;
    int wm = warp & 1, wn = warp >> 1;             // 2 x 4
    int m0 = blockIdx.y * 128, n0 = blockIdx.x * 128;

    uint32_t sAh_u = smem_u32(sA[0]), sAl_u = smem_u32(sA[1]);
    uint32_t sBh_u = smem_u32(sB[0]), sBl_u = smem_u32(sB[1]);

    float acc[4][4][4];
#pragma unroll
    for (int i = 0; i < 4; i++)
#pragma unroll
        for (int j = 0; j < 4; j++)
#pragma unroll
            for (int q = 0; q < 4; q++) acc[i][j][q] = 0.f;

    // per-thread copy geometry: 512 uint4 per tile, 2 per thread
    int e0 = tid, e1 = tid + 256;
    int r0 = e0 >> 2, c0 = (e0 & 3) * 8;
    int r1 = e1 >> 2, c1 = (e1 & 3) * 8;

    // A fragment address components
    int arow = lane & 15;
    int acolh = (lane >> 4) * 8;
    // B fragment address components
    int brow = (lane & 7) + ((lane >> 4) & 1) * 8;
    int bcolh = ((lane >> 3) & 1) * 8;

    for (int kt = 0; kt < KD; kt += 32) {
        __syncthreads();
        // copy 4 tiles (Ah, Al, Bh, Bl), each 128x32 bf16
        {
            const __nv_bfloat16* a_h = Ah + (size_t)m0 * KD + kt;
            const __nv_bfloat16* a_l = Al + (size_t)m0 * KD + kt;
            const __nv_bfloat16* b_h = Bh + (size_t)n0 * KD + kt;
            const __nv_bfloat16* b_l = Bl + (size_t)n0 * KD + kt;
            *(uint4*)&sA[0][r0 * SSTR + c0] = *(const uint4*)(a_h + (size_t)r0 * KD + c0);
            *(uint4*)&sA[0][r1 * SSTR + c1] = *(const uint4*)(a_h + (size_t)r1 * KD + c1);
            *(uint4*)&sA[1][r0 * SSTR + c0] = *(const uint4*)(a_l + (size_t)r0 * KD + c0);
            *(uint4*)&sA[1][r1 * SSTR + c1] = *(const uint4*)(a_l + (size_t)r1 * KD + c1);
            *(uint4*)&sB[0][r0 * SSTR + c0] = *(const uint4*)(b_h + (size_t)r0 * KD + c0);
            *(uint4*)&sB[0][r1 * SSTR + c1] = *(const uint4*)(b_h + (size_t)r1 * KD + c1);
            *(uint4*)&sB[1][r0 * SSTR + c0] = *(const uint4*)(b_l + (size_t)r0 * KD + c0);
            *(uint4*)&sB[1][r1 * SSTR + c1] = *(const uint4*)(b_l + (size_t)r1 * KD + c1);
        }
        __syncthreads();

#pragma unroll
        for (int ks = 0; ks < 32; ks += 16) {
            uint32_t ahf[4][4], alf[4][4];
#pragma unroll
            for (int mt = 0; mt < 4; mt++) {
                int r = wm * 64 + mt * 16 + arow;
                uint32_t off = (uint32_t)(r * SSTR + ks + acolh) * 2;
                ldmx4(ahf[mt][0], ahf[mt][1], ahf[mt][2], ahf[mt][3], sAh_u + off);
                ldmx4(alf[mt][0], alf[mt][1], alf[mt][2], alf[mt][3], sAl_u + off);
            }
            uint32_t bhf[4][2], blf[4][2];
#pragma unroll
            for (int ntp = 0; ntp < 2; ntp++) {
                int nb = wn * 32 + ntp * 16;
                uint32_t off = (uint32_t)((nb + brow) * SSTR + ks + bcolh) * 2;
                ldmx4(bhf[2*ntp][0], bhf[2*ntp][1], bhf[2*ntp+1][0], bhf[2*ntp+1][1], sBh_u + off);
                ldmx4(blf[2*ntp][0], blf[2*ntp][1], blf[2*ntp+1][0], blf[2*ntp+1][1], sBl_u + off);
            }
#pragma unroll
            for (int mt = 0; mt < 4; mt++)
#pragma unroll
                for (int nt = 0; nt < 4; nt++) {
                    mma_bf16(acc[mt][nt], ahf[mt], bhf[nt]);
                    mma_bf16(acc[mt][nt], ahf[mt], blf[nt]);
                    mma_bf16(acc[mt][nt], alf[mt], bhf[nt]);
                }
        }
    }

    // epilogue
#pragma unroll
    for (int mt = 0; mt < 4; mt++) {
        int r = m0 + wm * 64 + mt * 16 + (lane >> 2);
#pragma unroll
        for (int nt = 0; nt < 4; nt++) {
            int c = n0 + wn * 32 + nt * 8 + (lane & 3) * 2;
            float2 o0, o1;
            o0.x = (acc[mt][nt][0] + bias[c]) * scale;
            o0.y = (acc[mt][nt][1] + bias[c + 1]) * scale;
            o1.x = (acc[mt][nt][2] + bias[c]) * scale;
            o1.y = (acc[mt][nt][3] + bias[c + 1]) * scale;
            *(float2*)(C + (size_t)r * KD + c) = o0;
            *(float2*)(C + (size_t)(r + 8) * KD + c) = o1;
        }
    }
}

// ---------------- mask dtype auto-detect + normalize -------------------------
__global__ void mask_prep(const void* m) {
    __shared__ int mode;
    int tid = threadIdx.x;
    if (tid == 0) {
        const int* mi = (const int*)m;
        int ok_i = 1;
        for (int i = 0; i < 1024; i++) { int v = mi[i]; if (v != 0 && v != 1) { ok_i = 0; break; } }
        if (ok_i) mode = 0;
        else {
            const float* mf = (const float*)m;
            int ok_f = 1;
            for (int i = 0; i < 1024; i++) { float v = mf[i]; if (v != 0.0f && v != 1.0f) { ok_f = 0; break; } }
            mode = ok_f ? 1 : 2;
        }
    }
    __syncthreads();
    int md = mode;
    for (int i = tid; i < BSZ*TGT; i += blockDim.x) {
        bool b;
        if (md == 0)      b = ((const int*)m)[i] != 0;
        else if (md == 1) b = ((const float*)m)[i] != 0.0f;
        else              b = ((const unsigned char*)m)[i] != 0;
        g_mask[i] = b ? 1 : 0;
    }
}

// ------- scores: raw masked S tiles + per-tile row (max, sumexp) stats --------
__global__ __launch_bounds__(256) void scores_kernel(
    const float* __restrict__ q, const float* __restrict__ k, float* __restrict__ W)
{
    __shared__ float Qs[16][128];
    __shared__ float Ks[16][128];
    int bh = blockIdx.z;
    int b = bh >> 4;
    int base = b * EMB + (bh & 15) * HD;
    int m0 = blockIdx.y * 128, n0 = blockIdx.x * 128;
    int tile = blockIdx.x;
    int tid = threadIdx.x;
    int tx = tid & 15, ty = tid >> 4;

    float acc[8][8];
#pragma unroll
    for (int i = 0; i < 8; i++)
#pragma unroll
        for (int j = 0; j < 8; j++) acc[i][j] = 0.f;

    for (int kt = 0; kt < HD; kt += 16) {
#pragma unroll
        for (int i = 0; i < 2; i++) {
            int t4 = tid * 2 + i;
            int r = t4 >> 2, c = (t4 & 3) * 4;
            float4 va = *(const float4*)(q + (long long)(m0 + r) * (BSZ*EMB) + base + kt + c);
            Qs[c + 0][r] = va.x; Qs[c + 1][r] = va.y; Qs[c + 2][r] = va.z; Qs[c + 3][r] = va.w;
            float4 vb = *(const float4*)(k + (long long)(n0 + r) * (BSZ*EMB) + base + kt + c);
            Ks[c + 0][r] = vb.x; Ks[c + 1][r] = vb.y; Ks[c + 2][r] = vb.z; Ks[c + 3][r] = vb.w;
        }
        __syncthreads();
#pragma unroll
        for (int k2 = 0; k2 < 16; k2++) {
            float a[8], bb[8];
#pragma unroll
            for (int i = 0; i < 8; i++) a[i] = Qs[k2][ty * 8 + i];
#pragma unroll
            for (int j = 0; j < 8; j++) bb[j] = Ks[k2][tx * 8 + j];
#pragma unroll
            for (int i = 0; i < 8; i++)
#pragma unroll
                for (int j = 0; j < 8; j++) acc[i][j] += a[i] * bb[j];
        }
        __syncthreads();
    }

    unsigned char mk[8];
#pragma unroll
    for (int j = 0; j < 8; j++) mk[j] = g_mask[b * TGT + n0 + tx * 8 + j];

    long long wbase = (long long)bh * TGT * TGT;
#pragma unroll
    for (int i = 0; i < 8; i++) {
        int r = m0 + ty * 8 + i;
        float v[8];
        float mx = -INFINITY;
#pragma unroll
        for (int j = 0; j < 8; j++) {
            float x = acc[i][j];
            if (mk[j]) x = NEGMAX;
            v[j] = x;
            mx = fmaxf(mx, x);
        }
        float4* wp = (float4*)(W + wbase + (long long)r * TGT + n0 + tx * 8);
        wp[0] = make_float4(v[0], v[1], v[2], v[3]);
        wp[1] = make_float4(v[4], v[5], v[6], v[7]);
#pragma unroll
        for (int o = 8; o > 0; o >>= 1) mx = fmaxf(mx, __shfl_xor_sync(0xffffffffu, mx, o, 16));
        float se = 0.f;
#pragma unroll
        for (int j = 0; j < 8; j++) se += __expf(v[j] - mx);
#pragma unroll
        for (int o = 8; o > 0; o >>= 1) se += __shfl_xor_sync(0xffffffffu, se, o, 16);
        if (tx == 0) {
            int sidx = (bh * NTILE + tile) * TGT + r;
            g_tmax[sidx] = mx;
            g_tsum[sidx] = se;
        }
    }
}

// ------- combine per-tile stats into per-row (max, 1/sum) ---------------------
__global__ __launch_bounds__(256) void stats_combine()
{
    int idx = blockIdx.x * 256 + threadIdx.x;
    int bh = idx >> 11, row = idx & 2047;
    float gm = -INFINITY;
#pragma unroll
    for (int t = 0; t < NTILE; t++)
        gm = fmaxf(gm, g_tmax[(bh * NTILE + t) * TGT + row]);
    float s = 0.f;
#pragma unroll
    for (int t = 0; t < NTILE; t++)
        s += g_tsum[(bh * NTILE + t) * TGT + row] * __expf(g_tmax[(bh * NTILE + t) * TGT + row] - gm);
    g_rmax[idx] = gm;
    g_rinv[idx] = 1.0f / s;
}

// ------- AV with fused normalization ------------------------------------------
__global__ __launch_bounds__(256) void av_norm_kernel(
    float* __restrict__ W, const float* __restrict__ v, float* __restrict__ ctx)
{
    __shared__ float Ps[64][128];
    __shared__ float Vs[64][64];
    int bh = blockIdx.y;
    int b = bh >> 4;
    int base = b * EMB + (bh & 15) * HD;
    int m0 = blockIdx.x * 128;
    float* P = W + (long long)bh * TGT * TGT;
    int tid = threadIdx.x;
    int tx = tid & 15, ty = tid >> 4;

    int myrow = tid >> 1;
    int mycol0 = (tid & 1) * 32;
    float myrm  = g_rmax[bh * TGT + m0 + myrow];
    float myri  = g_rinv[bh * TGT + m0 + myrow];

    float acc[8][4];
#pragma unroll
    for (int i = 0; i < 8; i++)
#pragma unroll
        for (int j = 0; j < 4; j++) acc[i][j] = 0.f;

    for (int kt = 0; kt < TGT; kt += 64) {
        float* srow = P + (long long)(m0 + myrow) * TGT + kt + mycol0;
#pragma unroll
        for (int l = 0; l < 8; l++) {
            float4 s4 = *(float4*)(srow + l * 4);
            float4 p4;
            p4.x = __expf(s4.x - myrm) * myri;
            p4.y = __expf(s4.y - myrm) * myri;
            p4.z = __expf(s4.z - myrm) * myri;
            p4.w = __expf(s4.w - myrm) * myri;
            *(float4*)(srow + l * 4) = p4;
            int c = mycol0 + l * 4;
            Ps[c + 0][myrow] = p4.x;
            Ps[c + 1][myrow] = p4.y;
            Ps[c + 2][myrow] = p4.z;
            Ps[c + 3][myrow] = p4.w;
        }
#pragma unroll
        for (int l = 0; l < 4; l++) {
            int e = tid * 4 + l;
            int key = e >> 4, d = (e & 15) * 4;
            float4 v4 = *(const float4*)(v + (long long)(kt + key) * (BSZ*EMB) + base + d);
            *(float4*)&Vs[key][d] = v4;
        }
        __syncthreads();
#pragma unroll 4
        for (int k2 = 0; k2 < 64; k2++) {
            float4 a0 = *(const float4*)&Ps[k2][ty * 8];
            float4 a1 = *(const float4*)&Ps[k2][ty * 8 + 4];
            float4 bv = *(const float4*)&Vs[k2][tx * 4];
            float a[8] = {a0.x,a0.y,a0.z,a0.w,a1.x,a1.y,a1.z,a1.w};
            float bb[4] = {bv.x,bv.y,bv.z,bv.w};
#pragma unroll
            for (int i = 0; i < 8; i++)
#pragma unroll
                for (int j = 0; j < 4; j++) acc[i][j] += a[i] * bb[j];
        }
        __syncthreads();
    }
#pragma unroll
    for (int i = 0; i < 8; i++) {
        int t = m0 + ty * 8 + i;
#pragma unroll
        for (int j = 0; j < 4; j++) {
            int d = tx * 4 + j;
            ctx[(long long)(t * BSZ + b) * EMB + (bh & 15) * HD + d] = acc[i][j];
        }
    }
}

// ---------------- launch -----------------------------------------------------
extern "C" void kernel_launch(void* const* d_in, const int* in_sizes, int n_in,
                              void* d_out, int out_size)
{
    const float* query = (const float*)d_in[0];
    const void*  maskp = d_in[1];
    const float* qw = (const float*)d_in[2];
    const float* qb = (const float*)d_in[3];
    const float* kw = (const float*)d_in[4];
    const float* kb = (const float*)d_in[5];
    const float* vw = (const float*)d_in[6];
    const float* vb = (const float*)d_in[7];
    const float* ow = (const float*)d_in[8];
    const float* ob = (const float*)d_in[9];
    float* out = (float*)d_out;

    float *pq, *pk, *pv, *pctx, *pwf;
    cudaGetSymbolAddress((void**)&pq,   g_q);
    cudaGetSymbolAddress((void**)&pk,   g_k);
    cudaGetSymbolAddress((void**)&pv,   g_v);
    cudaGetSymbolAddress((void**)&pctx, g_ctx);
    cudaGetSymbolAddress((void**)&pwf,  g_wfallback);

    __nv_bfloat16 *ah, *al, *ch, *cl, *qwh, *qwl, *kwh, *kwl, *vwh, *vwl, *owh, *owl;
    cudaGetSymbolAddress((void**)&ah,  g_ah);  cudaGetSymbolAddress((void**)&al,  g_al);
    cudaGetSymbolAddress((void**)&ch,  g_ch);  cudaGetSymbolAddress((void**)&cl,  g_cl);
    cudaGetSymbolAddress((void**)&qwh, g_qwh); cudaGetSymbolAddress((void**)&qwl, g_qwl);
    cudaGetSymbolAddress((void**)&kwh, g_kwh); cudaGetSymbolAddress((void**)&kwl, g_kwl);
    cudaGetSymbolAddress((void**)&vwh, g_vwh); cudaGetSymbolAddress((void**)&vwl, g_vwl);
    cudaGetSymbolAddress((void**)&owh, g_owh); cudaGetSymbolAddress((void**)&owl, g_owl);

    float* W = ((long long)out_size >= (long long)ATTN_N + W_ELEMS) ? (out + ATTN_N) : pwf;

    mask_prep<<<1, 256>>>(maskp);

    split_kernel<<<ROWS*EMB/1024, 256>>>(query, ah, al, ROWS*EMB);
    split_kernel<<<EMB*EMB/1024, 256>>>(qw, qwh, qwl, EMB*EMB);
    split_kernel<<<EMB*EMB/1024, 256>>>(kw, kwh, kwl, EMB*EMB);
    split_kernel<<<EMB*EMB/1024, 256>>>(vw, vwh, vwl, EMB*EMB);
    split_kernel<<<EMB*EMB/1024, 256>>>(ow, owh, owl, EMB*EMB);

    dim3 gproj(EMB / 128, ROWS / 128);         // (8, 32)
    hgemm<<<gproj, 256>>>(ah, al, qwh, qwl, qb, pq, 0.125f);
    hgemm<<<gproj, 256>>>(ah, al, kwh, kwl, kb, pk, 1.0f);
    hgemm<<<gproj, 256>>>(ah, al, vwh, vwl, vb, pv, 1.0f);

    scores_kernel<<<dim3(TGT / 128, TGT / 128, BH), 256>>>(pq, pk, W);

    stats_combine<<<BH * TGT / 256, 256>>>();

    av_norm_kernel<<<dim3(TGT / 128, BH), 256>>>(W, pv, pctx);

    split_kernel<<<ROWS*EMB/1024, 256>>>(pctx, ch, cl, ROWS*EMB);
    hgemm<<<gproj, 256>>>(ch, cl, owh, owl, ob, out, 1.0f);
}

// round 6
// speedup vs baseline: 1.5027x; 1.0982x over previous
#include <cuda_runtime.h>
#include <cuda_bf16.h>
#include <math.h>
#include <stdint.h>

#define TGT 2048
#define BSZ 2
#define EMB 1024
#define NH 16
#define HD 64
#define ROWS (TGT*BSZ)              // 4096
#define BH (BSZ*NH)                 // 32
#define ATTN_N (ROWS*EMB)           // 4194304
#define W_ELEMS (134217728LL)       // 32*2048*2048
#define NEGMAX (-3.4028234663852886e38f)
#define NTILE 16                    // 2048/128 key tiles
#define KD 1024

// ---------------- scratch (static device memory; no allocations) -------------
__device__ float g_v[ROWS*EMB];
__device__ float g_wfallback[134217728];
__device__ unsigned char g_mask[BSZ*TGT];
__device__ float g_tmax[BH*NTILE*TGT];
__device__ float g_tsum[BH*NTILE*TGT];
__device__ float g_rmax[BH*TGT];
__device__ float g_rinv[BH*TGT];

// split-bf16 operands
__device__ __nv_bfloat16 g_ah[ROWS*EMB], g_al[ROWS*EMB];          // input query hi/lo
__device__ __nv_bfloat16 g_ch[ROWS*EMB], g_cl[ROWS*EMB];          // ctx hi/lo
__device__ __nv_bfloat16 g_qh[ROWS*EMB], g_ql[ROWS*EMB];          // projected q hi/lo
__device__ __nv_bfloat16 g_kh[ROWS*EMB], g_kl[ROWS*EMB];          // projected k hi/lo
__device__ __nv_bfloat16 g_qwh[EMB*EMB], g_qwl[EMB*EMB];
__device__ __nv_bfloat16 g_kwh[EMB*EMB], g_kwl[EMB*EMB];
__device__ __nv_bfloat16 g_vwh[EMB*EMB], g_vwl[EMB*EMB];
__device__ __nv_bfloat16 g_owh[EMB*EMB], g_owl[EMB*EMB];

// ---------------- helpers ----------------------------------------------------
__device__ __forceinline__ uint32_t smem_u32(const void* p) {
    uint32_t a;
    asm("{ .reg .u64 t; cvta.to.shared.u64 t, %1; cvt.u32.u64 %0, t; }" : "=r"(a) : "l"(p));
    return a;
}
__device__ __forceinline__ void ldmx4(uint32_t& r0, uint32_t& r1, uint32_t& r2, uint32_t& r3, uint32_t addr) {
    asm volatile("ldmatrix.sync.aligned.m8n8.x4.shared.b16 {%0,%1,%2,%3}, [%4];"
                 : "=r"(r0), "=r"(r1), "=r"(r2), "=r"(r3) : "r"(addr));
}
__device__ __forceinline__ void mma_bf16(float* d, const uint32_t* a, const uint32_t* b) {
    asm volatile("mma.sync.aligned.m16n8k16.row.col.f32.bf16.bf16.f32 "
                 "{%0,%1,%2,%3}, {%4,%5,%6,%7}, {%8,%9}, {%0,%1,%2,%3};"
                 : "+f"(d[0]), "+f"(d[1]), "+f"(d[2]), "+f"(d[3])
                 : "r"(a[0]), "r"(a[1]), "r"(a[2]), "r"(a[3]), "r"(b[0]), "r"(b[1]));
}
__device__ __forceinline__ void split1(float x, __nv_bfloat16& h, __nv_bfloat16& l) {
    h = __float2bfloat16_rn(x);
    l = __float2bfloat16_rn(x - __bfloat162float(h));
}

// ---------------- fp32 -> (hi, lo) bf16 split --------------------------------
__global__ __launch_bounds__(256) void split_kernel(const float* __restrict__ in,
                                                    __nv_bfloat16* __restrict__ hi,
                                                    __nv_bfloat16* __restrict__ lo, int n)
{
    int i = (blockIdx.x * 256 + threadIdx.x) * 4;
    if (i >= n) return;
    float4 x = *(const float4*)(in + i);
    __nv_bfloat162 hh0, hh1, ll0, ll1;
    split1(x.x, hh0.x, ll0.x); split1(x.y, hh0.y, ll0.y);
    split1(x.z, hh1.x, ll1.x); split1(x.w, hh1.y, ll1.y);
    *(__nv_bfloat162*)(hi + i) = hh0; *(__nv_bfloat162*)(hi + i + 2) = hh1;
    *(__nv_bfloat162*)(lo + i) = ll0; *(__nv_bfloat162*)(lo + i + 2) = ll1;
}

// ---------------- split-bf16 HMMA NT GEMM ------------------------------------
// C = (Ah+Al)[M,1024] @ (Bh+Bl)[1024,1024]^T + bias, *scale.
// Output: fp32 Cf and/or split-bf16 (Chi, Clo). 128x128 tile, 8 warps 2x4.
#define SSTR 40

__global__ __launch_bounds__(256, 2) void hgemm(
    const __nv_bfloat16* __restrict__ Ah, const __nv_bfloat16* __restrict__ Al,
    const __nv_bfloat16* __restrict__ Bh, const __nv_bfloat16* __restrict__ Bl,
    const float* __restrict__ bias, float* __restrict__ Cf,
    __nv_bfloat16* __restrict__ Chi, __nv_bfloat16* __restrict__ Clo, float scale)
{
    __shared__ __align__(16) __nv_bfloat16 sA[2][128 * SSTR];
    __shared__ __align__(16) __nv_bfloat16 sB[2][128 * SSTR];

    int tid = threadIdx.x;
    int warp = tid >> 5, lane = tid & 31;
    int wm = warp & 1, wn = warp >> 1;
    int m0 = blockIdx.y * 128, n0 = blockIdx.x * 128;

    uint32_t sAh_u = smem_u32(sA[0]), sAl_u = smem_u32(sA[1]);
    uint32_t sBh_u = smem_u32(sB[0]), sBl_u = smem_u32(sB[1]);

    float acc[4][4][4];
#pragma unroll
    for (int i = 0; i < 4; i++)
#pragma unroll
        for (int j = 0; j < 4; j++)
#pragma unroll
            for (int q = 0; q < 4; q++) acc[i][j][q] = 0.f;

    int e0 = tid, e1 = tid + 256;
    int r0 = e0 >> 2, c0 = (e0 & 3) * 8;
    int r1 = e1 >> 2, c1 = (e1 & 3) * 8;

    int arow = lane & 15;
    int acolh = (lane >> 4) * 8;
    int brow = (lane & 7) + ((lane >> 4) & 1) * 8;
    int bcolh = ((lane >> 3) & 1) * 8;

    for (int kt = 0; kt < KD; kt += 32) {
        __syncthreads();
        {
            const __nv_bfloat16* a_h = Ah + (size_t)m0 * KD + kt;
            const __nv_bfloat16* a_l = Al + (size_t)m0 * KD + kt;
            const __nv_bfloat16* b_h = Bh + (size_t)n0 * KD + kt;
            const __nv_bfloat16* b_l = Bl + (size_t)n0 * KD + kt;
            *(uint4*)&sA[0][r0 * SSTR + c0] = *(const uint4*)(a_h + (size_t)r0 * KD + c0);
            *(uint4*)&sA[0][r1 * SSTR + c1] = *(const uint4*)(a_h + (size_t)r1 * KD + c1);
            *(uint4*)&sA[1][r0 * SSTR + c0] = *(const uint4*)(a_l + (size_t)r0 * KD + c0);
            *(uint4*)&sA[1][r1 * SSTR + c1] = *(const uint4*)(a_l + (size_t)r1 * KD + c1);
            *(uint4*)&sB[0][r0 * SSTR + c0] = *(const uint4*)(b_h + (size_t)r0 * KD + c0);
            *(uint4*)&sB[0][r1 * SSTR + c1] = *(const uint4*)(b_h + (size_t)r1 * KD + c1);
            *(uint4*)&sB[1][r0 * SSTR + c0] = *(const uint4*)(b_l + (size_t)r0 * KD + c0);
            *(uint4*)&sB[1][r1 * SSTR + c1] = *(const uint4*)(b_l + (size_t)r1 * KD + c1);
        }
        __syncthreads();

#pragma unroll
        for (int ks = 0; ks < 32; ks += 16) {
            uint32_t ahf[4][4], alf[4][4];
#pragma unroll
            for (int mt = 0; mt < 4; mt++) {
                int r = wm * 64 + mt * 16 + arow;
                uint32_t off = (uint32_t)(r * SSTR + ks + acolh) * 2;
                ldmx4(ahf[mt][0], ahf[mt][1], ahf[mt][2], ahf[mt][3], sAh_u + off);
                ldmx4(alf[mt][0], alf[mt][1], alf[mt][2], alf[mt][3], sAl_u + off);
            }
            uint32_t bhf[4][2], blf[4][2];
#pragma unroll
            for (int ntp = 0; ntp < 2; ntp++) {
                int nb = wn * 32 + ntp * 16;
                uint32_t off = (uint32_t)((nb + brow) * SSTR + ks + bcolh) * 2;
                ldmx4(bhf[2*ntp][0], bhf[2*ntp][1], bhf[2*ntp+1][0], bhf[2*ntp+1][1], sBh_u + off);
                ldmx4(blf[2*ntp][0], blf[2*ntp][1], blf[2*ntp+1][0], blf[2*ntp+1][1], sBl_u + off);
            }
#pragma unroll
            for (int mt = 0; mt < 4; mt++)
#pragma unroll
                for (int nt = 0; nt < 4; nt++) {
                    mma_bf16(acc[mt][nt], ahf[mt], bhf[nt]);
                    mma_bf16(acc[mt][nt], ahf[mt], blf[nt]);
                    mma_bf16(acc[mt][nt], alf[mt], bhf[nt]);
                }
        }
    }

#pragma unroll
    for (int mt = 0; mt < 4; mt++) {
        int r = m0 + wm * 64 + mt * 16 + (lane >> 2);
#pragma unroll
        for (int nt = 0; nt < 4; nt++) {
            int c = n0 + wn * 32 + nt * 8 + (lane & 3) * 2;
            float2 o0, o1;
            o0.x = (acc[mt][nt][0] + bias[c]) * scale;
            o0.y = (acc[mt][nt][1] + bias[c + 1]) * scale;
            o1.x = (acc[mt][nt][2] + bias[c]) * scale;
            o1.y = (acc[mt][nt][3] + bias[c + 1]) * scale;
            if (Cf) {
                *(float2*)(Cf + (size_t)r * KD + c) = o0;
                *(float2*)(Cf + (size_t)(r + 8) * KD + c) = o1;
            }
            if (Chi) {
                __nv_bfloat162 h0, l0, h1, l1;
                split1(o0.x, h0.x, l0.x); split1(o0.y, h0.y, l0.y);
                split1(o1.x, h1.x, l1.x); split1(o1.y, h1.y, l1.y);
                *(__nv_bfloat162*)(Chi + (size_t)r * KD + c) = h0;
                *(__nv_bfloat162*)(Clo + (size_t)r * KD + c) = l0;
                *(__nv_bfloat162*)(Chi + (size_t)(r + 8) * KD + c) = h1;
                *(__nv_bfloat162*)(Clo + (size_t)(r + 8) * KD + c) = l1;
            }
        }
    }
}

// ---------------- HMMA scores: S = Q@K^T (masked) + per-tile stats -----------
// smem (halves): Qh 0, Ql 9216, Kh 18432, Kl 27648; floats sMax@73728B, sSum@75776B
#define SC_QH 0
#define SC_QL 9216
#define SC_KH 18432
#define SC_KL 27648
#define SC_SMEM 77824
#define SST 72

__global__ __launch_bounds__(256) void hscores(
    const __nv_bfloat16* __restrict__ qh, const __nv_bfloat16* __restrict__ ql,
    const __nv_bfloat16* __restrict__ kh, const __nv_bfloat16* __restrict__ kl,
    float* __restrict__ W)
{
    extern __shared__ __align__(16) char smraw[];
    __nv_bfloat16* S = (__nv_bfloat16*)smraw;
    float* sMax = (float*)(smraw + 73728);
    float* sSum = (float*)(smraw + 75776);
    uint32_t sb = smem_u32(smraw);

    int bh = blockIdx.z;
    int b = bh >> 4;
    int base = b * EMB + (bh & 15) * HD;
    int n0 = blockIdx.x * 128, m0 = blockIdx.y * 128;
    int tid = threadIdx.x;
    int warp = tid >> 5, lane = tid & 31;
    int wm = warp & 1, wn = warp >> 1;

    // copy Q/K tiles (128 rows x 64 halves each, 4 tiles)
#pragma unroll
    for (int l = 0; l < 4; l++) {
        int e = tid + 256 * l;
        int row = e >> 3, c8 = (e & 7) * 8;
        size_t qa = (size_t)(m0 + row) * (BSZ*EMB) + base + c8;
        size_t ka = (size_t)(n0 + row) * (BSZ*EMB) + base + c8;
        int so = row * SST + c8;
        *(uint4*)&S[SC_QH + so] = *(const uint4*)(qh + qa);
        *(uint4*)&S[SC_QL + so] = *(const uint4*)(ql + qa);
        *(uint4*)&S[SC_KH + so] = *(const uint4*)(kh + ka);
        *(uint4*)&S[SC_KL + so] = *(const uint4*)(kl + ka);
    }
    __syncthreads();

    float acc[4][4][4];
#pragma unroll
    for (int i = 0; i < 4; i++)
#pragma unroll
        for (int j = 0; j < 4; j++)
#pragma unroll
            for (int q = 0; q < 4; q++) acc[i][j][q] = 0.f;

    int arow = lane & 15;
    int acolh = (lane >> 4) * 8;
    int brow = (lane & 7) + ((lane >> 4) & 1) * 8;
    int bcolh = ((lane >> 3) & 1) * 8;

#pragma unroll
    for (int ks = 0; ks < 64; ks += 16) {
        uint32_t qhf[4][4], qlf[4][4];
#pragma unroll
        for (int mt = 0; mt < 4; mt++) {
            int r = wm * 64 + mt * 16 + arow;
            uint32_t off = sb + (uint32_t)(r * SST + ks + acolh) * 2;
            ldmx4(qhf[mt][0], qhf[mt][1], qhf[mt][2], qhf[mt][3], off + SC_QH * 2);
            ldmx4(qlf[mt][0], qlf[mt][1], qlf[mt][2], qlf[mt][3], off + SC_QL * 2);
        }
        uint32_t khf[4][2], klf[4][2];
#pragma unroll
        for (int ntp = 0; ntp < 2; ntp++) {
            int nb = wn * 32 + ntp * 16;
            uint32_t off = sb + (uint32_t)((nb + brow) * SST + ks + bcolh) * 2;
            ldmx4(khf[2*ntp][0], khf[2*ntp][1], khf[2*ntp+1][0], khf[2*ntp+1][1], off + SC_KH * 2);
            ldmx4(klf[2*ntp][0], klf[2*ntp][1], klf[2*ntp+1][0], klf[2*ntp+1][1], off + SC_KL * 2);
        }
#pragma unroll
        for (int mt = 0; mt < 4; mt++)
#pragma unroll
            for (int nt = 0; nt < 4; nt++) {
                mma_bf16(acc[mt][nt], qhf[mt], khf[nt]);
                mma_bf16(acc[mt][nt], qhf[mt], klf[nt]);
                mma_bf16(acc[mt][nt], qlf[mt], khf[nt]);
            }
    }

    // epilogue: mask, write raw S, per-row tile stats
    int qr = lane >> 2, qc = (lane & 3) * 2;
    unsigned char mk[4][2];
#pragma unroll
    for (int nt = 0; nt < 4; nt++) {
        int c = n0 + wn * 32 + nt * 8 + qc;
        mk[nt][0] = g_mask[b * TGT + c];
        mk[nt][1] = g_mask[b * TGT + c + 1];
    }
    long long wbase = (long long)bh * TGT * TGT;

#pragma unroll
    for (int mt = 0; mt < 4; mt++) {
        int rl = wm * 64 + mt * 16 + qr;   // local row (0..127)
        int rg = m0 + rl;
        float v0[8], v1[8];
#pragma unroll
        for (int nt = 0; nt < 4; nt++) {
            float x;
            x = acc[mt][nt][0]; if (mk[nt][0]) x = NEGMAX; v0[2*nt]   = x;
            x = acc[mt][nt][1]; if (mk[nt][1]) x = NEGMAX; v0[2*nt+1] = x;
            x = acc[mt][nt][2]; if (mk[nt][0]) x = NEGMAX; v1[2*nt]   = x;
            x = acc[mt][nt][3]; if (mk[nt][1]) x = NEGMAX; v1[2*nt+1] = x;
        }
#pragma unroll
        for (int nt = 0; nt < 4; nt++) {
            int c = n0 + wn * 32 + nt * 8 + qc;
            *(float2*)(W + wbase + (long long)rg * TGT + c) = make_float2(v0[2*nt], v0[2*nt+1]);
            *(float2*)(W + wbase + (long long)(rg + 8) * TGT + c) = make_float2(v1[2*nt], v1[2*nt+1]);
        }
        float mx0 = v0[0], mx1 = v1[0];
#pragma unroll
        for (int j = 1; j < 8; j++) { mx0 = fmaxf(mx0, v0[j]); mx1 = fmaxf(mx1, v1[j]); }
#pragma unroll
        for (int o = 1; o <= 2; o <<= 1) {
            mx0 = fmaxf(mx0, __shfl_xor_sync(0xffffffffu, mx0, o));
            mx1 = fmaxf(mx1, __shfl_xor_sync(0xffffffffu, mx1, o));
        }
        float se0 = 0.f, se1 = 0.f;
#pragma unroll
        for (int j = 0; j < 8; j++) { se0 += __expf(v0[j] - mx0); se1 += __expf(v1[j] - mx1); }
#pragma unroll
        for (int o = 1; o <= 2; o <<= 1) {
            se0 += __shfl_xor_sync(0xffffffffu, se0, o);
            se1 += __shfl_xor_sync(0xffffffffu, se1, o);
        }
        if ((lane & 3) == 0) {
            sMax[rl * 4 + wn] = mx0;       sSum[rl * 4 + wn] = se0;
            sMax[(rl + 8) * 4 + wn] = mx1; sSum[(rl + 8) * 4 + wn] = se1;
        }
    }
    __syncthreads();
    if (tid < 128) {
        float m0v = sMax[tid*4], m1v = sMax[tid*4+1], m2v = sMax[tid*4+2], m3v = sMax[tid*4+3];
        float gm = fmaxf(fmaxf(m0v, m1v), fmaxf(m2v, m3v));
        float s = sSum[tid*4] * __expf(m0v - gm) + sSum[tid*4+1] * __expf(m1v - gm)
                + sSum[tid*4+2] * __expf(m2v - gm) + sSum[tid*4+3] * __expf(m3v - gm);
        int sidx = (bh * NTILE + blockIdx.x) * TGT + m0 + tid;
        g_tmax[sidx] = gm;
        g_tsum[sidx] = s;
    }
}

// ------- combine per-tile stats into per-row (max, 1/sum) ---------------------
__global__ __launch_bounds__(256) void stats_combine()
{
    int idx = blockIdx.x * 256 + threadIdx.x;
    int bh = idx >> 11, row = idx & 2047;
    float gm = -INFINITY;
#pragma unroll
    for (int t = 0; t < NTILE; t++)
        gm = fmaxf(gm, g_tmax[(bh * NTILE + t) * TGT + row]);
    float s = 0.f;
#pragma unroll
    for (int t = 0; t < NTILE; t++)
        s += g_tsum[(bh * NTILE + t) * TGT + row] * __expf(g_tmax[(bh * NTILE + t) * TGT + row] - gm);
    g_rmax[idx] = gm;
    g_rinv[idx] = 1.0f / s;
}

// ---------------- HMMA AV: normalize S in place (-> P output) + ctx = P@V ----
// smem halves: Ph 0, Pl 9216, Vh 18432, Vl 23040; total 55296 B
#define AV_PH 0
#define AV_PL 9216
#define AV_VH 18432
#define AV_VL 23040
#define AV_SMEM 55296

__global__ __launch_bounds__(256) void hav(
    float* __restrict__ W, const float* __restrict__ v,
    __nv_bfloat16* __restrict__ ch, __nv_bfloat16* __restrict__ cl)
{
    extern __shared__ __align__(16) char smraw[];
    __nv_bfloat16* S = (__nv_bfloat16*)smraw;
    uint32_t sb = smem_u32(smraw);

    int bh = blockIdx.y;
    int b = bh >> 4;
    int base = b * EMB + (bh & 15) * HD;
    int m0 = blockIdx.x * 128;
    float* P = W + (long long)bh * TGT * TGT;
    int tid = threadIdx.x;
    int warp = tid >> 5, lane = tid & 31;
    int wm = warp & 3, wn = warp >> 2;

    int myrow = tid >> 1;
    int mycol0 = (tid & 1) * 32;
    float rm = g_rmax[bh * TGT + m0 + myrow];
    float ri = g_rinv[bh * TGT + m0 + myrow];

    int arow = lane & 15;
    int acolh = (lane >> 4) * 8;
    int brow = (lane & 7) + ((lane >> 4) & 1) * 8;
    int bcolh = ((lane >> 3) & 1) * 8;
    int vkey = tid >> 2, vd0 = (tid & 3) * 16;

    float acc[2][4][4];
#pragma unroll
    for (int i = 0; i < 2; i++)
#pragma unroll
        for (int j = 0; j < 4; j++)
#pragma unroll
            for (int q = 0; q < 4; q++) acc[i][j][q] = 0.f;

    for (int kt = 0; kt < TGT; kt += 64) {
        // P: normalize 128x64 chunk, write gmem, split into smem
        float* srow = P + (long long)(m0 + myrow) * TGT + kt + mycol0;
#pragma unroll
        for (int l = 0; l < 8; l++) {
            float4 s4 = *(float4*)(srow + l * 4);
            float4 p4;
            p4.x = __expf(s4.x - rm) * ri;
            p4.y = __expf(s4.y - rm) * ri;
            p4.z = __expf(s4.z - rm) * ri;
            p4.w = __expf(s4.w - rm) * ri;
            *(float4*)(srow + l * 4) = p4;
            int c = mycol0 + l * 4;
            __nv_bfloat162 h0, l0, h1, l1;
            split1(p4.x, h0.x, l0.x); split1(p4.y, h0.y, l0.y);
            split1(p4.z, h1.x, l1.x); split1(p4.w, h1.y, l1.y);
            int so = myrow * SST + c;
            *(__nv_bfloat162*)&S[AV_PH + so] = h0;
            *(__nv_bfloat162*)&S[AV_PH + so + 2] = h1;
            *(__nv_bfloat162*)&S[AV_PL + so] = l0;
            *(__nv_bfloat162*)&S[AV_PL + so + 2] = l1;
        }
        // V: 64 keys x 64 d, split + transpose into smem [d][key]
        const float* vp = v + (size_t)(kt + vkey) * (BSZ*EMB) + base + vd0;
#pragma unroll
        for (int j = 0; j < 4; j++) {
            float4 v4 = *(const float4*)(vp + j * 4);
            float vv[4] = {v4.x, v4.y, v4.z, v4.w};
#pragma unroll
            for (int m = 0; m < 4; m++) {
                int d = vd0 + j * 4 + m;
                __nv_bfloat16 h, l;
                split1(vv[m], h, l);
                S[AV_VH + d * SST + vkey] = h;
                S[AV_VL + d * SST + vkey] = l;
            }
        }
        __syncthreads();

#pragma unroll
        for (int ks = 0; ks < 64; ks += 16) {
            uint32_t pah[2][4], pal[2][4];
#pragma unroll
            for (int mt = 0; mt < 2; mt++) {
                int r = wm * 32 + mt * 16 + arow;
                uint32_t off = sb + (uint32_t)(r * SST + ks + acolh) * 2;
                ldmx4(pah[mt][0], pah[mt][1], pah[mt][2], pah[mt][3], off + AV_PH * 2);
                ldmx4(pal[mt][0], pal[mt][1], pal[mt][2], pal[mt][3], off + AV_PL * 2);
            }
            uint32_t bvh[4][2], bvl[4][2];
#pragma unroll
            for (int ntp = 0; ntp < 2; ntp++) {
                int nb = wn * 32 + ntp * 16;
                uint32_t off = sb + (uint32_t)((nb + brow) * SST + ks + bcolh) * 2;
                ldmx4(bvh[2*ntp][0], bvh[2*ntp][1], bvh[2*ntp+1][0], bvh[2*ntp+1][1], off + AV_VH * 2);
                ldmx4(bvl[2*ntp][0], bvl[2*ntp][1], bvl[2*ntp+1][0], bvl[2*ntp+1][1], off + AV_VL * 2);
            }
#pragma unroll
            for (int mt = 0; mt < 2; mt++)
#pragma unroll
                for (int nt = 0; nt < 4; nt++) {
                    mma_bf16(acc[mt][nt], pah[mt], bvh[nt]);
                    mma_bf16(acc[mt][nt], pah[mt], bvl[nt]);
                    mma_bf16(acc[mt][nt], pal[mt], bvh[nt]);
                }
        }
        __syncthreads();
    }

    // epilogue: write ctx split-bf16 in (t*BSZ+b, h*64+d) layout
    int qr = lane >> 2, qc = (lane & 3) * 2;
#pragma unroll
    for (int mt = 0; mt < 2; mt++) {
        int t = m0 + wm * 32 + mt * 16 + qr;
#pragma unroll
        for (int nt = 0; nt < 4; nt++) {
            int d = wn * 32 + nt * 8 + qc;
            size_t i0 = (size_t)(t * BSZ + b) * EMB + (bh & 15) * HD + d;
            size_t i1 = (size_t)((t + 8) * BSZ + b) * EMB + (bh & 15) * HD + d;
            __nv_bfloat162 h0, l0, h1, l1;
            split1(acc[mt][nt][0], h0.x, l0.x); split1(acc[mt][nt][1], h0.y, l0.y);
            split1(acc[mt][nt][2], h1.x, l1.x); split1(acc[mt][nt][3], h1.y, l1.y);
            *(__nv_bfloat162*)(ch + i0) = h0;
            *(__nv_bfloat162*)(cl + i0) = l0;
            *(__nv_bfloat162*)(ch + i1) = h1;
            *(__nv_bfloat162*)(cl + i1) = l1;
        }
    }
}

// ---------------- mask dtype auto-detect + normalize -------------------------
__global__ void mask_prep(const void* m) {
    __shared__ int mode;
    int tid = threadIdx.x;
    if (tid == 0) {
        const int* mi = (const int*)m;
        int ok_i = 1;
        for (int i = 0; i < 1024; i++) { int v = mi[i]; if (v != 0 && v != 1) { ok_i = 0; break; } }
        if (ok_i) mode = 0;
        else {
            const float* mf = (const float*)m;
            int ok_f = 1;
            for (int i = 0; i < 1024; i++) { float v = mf[i]; if (v != 0.0f && v != 1.0f) { ok_f = 0; break; } }
            mode = ok_f ? 1 : 2;
        }
    }
    __syncthreads();
    int md = mode;
    for (int i = tid; i < BSZ*TGT; i += blockDim.x) {
        bool b;
        if (md == 0)      b = ((const int*)m)[i] != 0;
        else if (md == 1) b = ((const float*)m)[i] != 0.0f;
        else              b = ((const unsigned char*)m)[i] != 0;
        g_mask[i] = b ? 1 : 0;
    }
}

// ---------------- launch -----------------------------------------------------
extern "C" void kernel_launch(void* const* d_in, const int* in_sizes, int n_in,
                              void* d_out, int out_size)
{
    const float* query = (const float*)d_in[0];
    const void*  maskp = d_in[1];
    const float* qw = (const float*)d_in[2];
    const float* qb = (const float*)d_in[3];
    const float* kw = (const float*)d_in[4];
    const float* kb = (const float*)d_in[5];
    const float* vw = (const float*)d_in[6];
    const float* vb = (const float*)d_in[7];
    const float* ow = (const float*)d_in[8];
    const float* ob = (const float*)d_in[9];
    float* out = (float*)d_out;

    float *pv, *pwf;
    cudaGetSymbolAddress((void**)&pv,  g_v);
    cudaGetSymbolAddress((void**)&pwf, g_wfallback);

    __nv_bfloat16 *ah, *al, *ch, *cl, *qh_, *ql_, *kh_, *kl_;
    __nv_bfloat16 *qwh, *qwl, *kwh, *kwl, *vwh, *vwl, *owh, *owl;
    cudaGetSymbolAddress((void**)&ah,  g_ah);  cudaGetSymbolAddress((void**)&al,  g_al);
    cudaGetSymbolAddress((void**)&ch,  g_ch);  cudaGetSymbolAddress((void**)&cl,  g_cl);
    cudaGetSymbolAddress((void**)&qh_, g_qh);  cudaGetSymbolAddress((void**)&ql_, g_ql);
    cudaGetSymbolAddress((void**)&kh_, g_kh);  cudaGetSymbolAddress((void**)&kl_, g_kl);
    cudaGetSymbolAddress((void**)&qwh, g_qwh); cudaGetSymbolAddress((void**)&qwl, g_qwl);
    cudaGetSymbolAddress((void**)&kwh, g_kwh); cudaGetSymbolAddress((void**)&kwl, g_kwl);
    cudaGetSymbolAddress((void**)&vwh, g_vwh); cudaGetSymbolAddress((void**)&vwl, g_vwl);
    cudaGetSymbolAddress((void**)&owh, g_owh); cudaGetSymbolAddress((void**)&owl, g_owl);

    float* W = ((long long)out_size >= (long long)ATTN_N + W_ELEMS) ? (out + ATTN_N) : pwf;

    cudaFuncSetAttribute(hscores, cudaFuncAttributeMaxDynamicSharedMemorySize, SC_SMEM);
    cudaFuncSetAttribute(hav, cudaFuncAttributeMaxDynamicSharedMemorySize, AV_SMEM);

    mask_prep<<<1, 256>>>(maskp);

    split_kernel<<<ROWS*EMB/1024, 256>>>(query, ah, al, ROWS*EMB);
    split_kernel<<<EMB*EMB/1024, 256>>>(qw, qwh, qwl, EMB*EMB);
    split_kernel<<<EMB*EMB/1024, 256>>>(kw, kwh, kwl, EMB*EMB);
    split_kernel<<<EMB*EMB/1024, 256>>>(vw, vwh, vwl, EMB*EMB);
    split_kernel<<<EMB*EMB/1024, 256>>>(ow, owh, owl, EMB*EMB);

    dim3 gproj(EMB / 128, ROWS / 128);         // (8, 32)
    hgemm<<<gproj, 256>>>(ah, al, qwh, qwl, qb, nullptr, qh_, ql_, 0.125f);
    hgemm<<<gproj, 256>>>(ah, al, kwh, kwl, kb, nullptr, kh_, kl_, 1.0f);
    hgemm<<<gproj, 256>>>(ah, al, vwh, vwl, vb, pv, nullptr, nullptr, 1.0f);

    hscores<<<dim3(TGT / 128, TGT / 128, BH), 256, SC_SMEM>>>(qh_, ql_, kh_, kl_, W);

    stats_combine<<<BH * TGT / 256, 256>>>();

    hav<<<dim3(TGT / 128, BH), 256, AV_SMEM>>>(W, pv, ch, cl);

    hgemm<<<gproj, 256>>>(ch, cl, owh, owl, ob, out, nullptr, nullptr, 1.0f);
}

// round 7
// speedup vs baseline: 1.5262x; 1.0156x over previous
#include <cuda_runtime.h>
#include <cuda_bf16.h>
#include <math.h>
#include <stdint.h>

#define TGT 2048
#define BSZ 2
#define EMB 1024
#define NH 16
#define HD 64
#define ROWS (TGT*BSZ)              // 4096
#define BH (BSZ*NH)                 // 32
#define ATTN_N (ROWS*EMB)           // 4194304
#define W_ELEMS (134217728LL)       // 32*2048*2048
#define NEGMAX (-3.4028234663852886e38f)
#define NTILE 16                    // 2048/128 key tiles
#define KD 1024

// ---------------- scratch (static device memory; no allocations) -------------
__device__ float g_v[ROWS*EMB];
__device__ float g_wfallback[134217728];
__device__ unsigned char g_mask[BSZ*TGT];
__device__ float g_tmax[BH*NTILE*TGT];
__device__ float g_tsum[BH*NTILE*TGT];
__device__ float g_rmax[BH*TGT];
__device__ float g_rinv[BH*TGT];

// split-bf16 operands
__device__ __nv_bfloat16 g_ah[ROWS*EMB], g_al[ROWS*EMB];          // input query hi/lo
__device__ __nv_bfloat16 g_ch[ROWS*EMB], g_cl[ROWS*EMB];          // ctx hi/lo
__device__ __nv_bfloat16 g_qh[ROWS*EMB], g_ql[ROWS*EMB];          // projected q hi/lo
__device__ __nv_bfloat16 g_kh[ROWS*EMB], g_kl[ROWS*EMB];          // projected k hi/lo
__device__ __nv_bfloat16 g_qwh[EMB*EMB], g_qwl[EMB*EMB];
__device__ __nv_bfloat16 g_kwh[EMB*EMB], g_kwl[EMB*EMB];
__device__ __nv_bfloat16 g_vwh[EMB*EMB], g_vwl[EMB*EMB];
__device__ __nv_bfloat16 g_owh[EMB*EMB], g_owl[EMB*EMB];

// ---------------- helpers ----------------------------------------------------
__device__ __forceinline__ uint32_t smem_u32(const void* p) {
    uint32_t a;
    asm("{ .reg .u64 t; cvta.to.shared.u64 t, %1; cvt.u32.u64 %0, t; }" : "=r"(a) : "l"(p));
    return a;
}
__device__ __forceinline__ void ldmx4(uint32_t& r0, uint32_t& r1, uint32_t& r2, uint32_t& r3, uint32_t addr) {
    asm volatile("ldmatrix.sync.aligned.m8n8.x4.shared.b16 {%0,%1,%2,%3}, [%4];"
                 : "=r"(r0), "=r"(r1), "=r"(r2), "=r"(r3) : "r"(addr));
}
__device__ __forceinline__ void mma_bf16(float* d, const uint32_t* a, const uint32_t* b) {
    asm volatile("mma.sync.aligned.m16n8k16.row.col.f32.bf16.bf16.f32 "
                 "{%0,%1,%2,%3}, {%4,%5,%6,%7}, {%8,%9}, {%0,%1,%2,%3};"
                 : "+f"(d[0]), "+f"(d[1]), "+f"(d[2]), "+f"(d[3])
                 : "r"(a[0]), "r"(a[1]), "r"(a[2]), "r"(a[3]), "r"(b[0]), "r"(b[1]));
}
__device__ __forceinline__ void split1(float x, __nv_bfloat16& h, __nv_bfloat16& l) {
    h = __float2bfloat16_rn(x);
    l = __float2bfloat16_rn(x - __bfloat162float(h));
}

// ---------------- fp32 -> (hi, lo) bf16 split --------------------------------
__global__ __launch_bounds__(256) void split_kernel(const float* __restrict__ in,
                                                    __nv_bfloat16* __restrict__ hi,
                                                    __nv_bfloat16* __restrict__ lo, int n)
{
    int i = (blockIdx.x * 256 + threadIdx.x) * 4;
    if (i >= n) return;
    float4 x = *(const float4*)(in + i);
    __nv_bfloat162 hh0, hh1, ll0, ll1;
    split1(x.x, hh0.x, ll0.x); split1(x.y, hh0.y, ll0.y);
    split1(x.z, hh1.x, ll1.x); split1(x.w, hh1.y, ll1.y);
    *(__nv_bfloat162*)(hi + i) = hh0; *(__nv_bfloat162*)(hi + i + 2) = hh1;
    *(__nv_bfloat162*)(lo + i) = ll0; *(__nv_bfloat162*)(lo + i + 2) = ll1;
}

// ---------------- split-bf16 HMMA NT GEMM ------------------------------------
// C = (Ah+Al)[M,1024] @ (Bh+Bl)[1024,1024]^T + bias, *scale.
// Output: fp32 Cf and/or split-bf16 (Chi, Clo). 128x128 tile, 8 warps 2x4.
#define SSTR 40

__global__ __launch_bounds__(256, 2) void hgemm(
    const __nv_bfloat16* __restrict__ Ah, const __nv_bfloat16* __restrict__ Al,
    const __nv_bfloat16* __restrict__ Bh, const __nv_bfloat16* __restrict__ Bl,
    const float* __restrict__ bias, float* __restrict__ Cf,
    __nv_bfloat16* __restrict__ Chi, __nv_bfloat16* __restrict__ Clo, float scale)
{
    __shared__ __align__(16) __nv_bfloat16 sA[2][128 * SSTR];
    __shared__ __align__(16) __nv_bfloat16 sB[2][128 * SSTR];

    int tid = threadIdx.x;
    int warp = tid >> 5, lane = tid & 31;
    int wm = warp & 1, wn = warp >> 1;
    int m0 = blockIdx.y * 128, n0 = blockIdx.x * 128;

    uint32_t sAh_u = smem_u32(sA[0]), sAl_u = smem_u32(sA[1]);
    uint32_t sBh_u = smem_u32(sB[0]), sBl_u = smem_u32(sB[1]);

    float acc[4][4][4];
#pragma unroll
    for (int i = 0; i < 4; i++)
#pragma unroll
        for (int j = 0; j < 4; j++)
#pragma unroll
            for (int q = 0; q < 4; q++) acc[i][j][q] = 0.f;

    int e0 = tid, e1 = tid + 256;
    int r0 = e0 >> 2, c0 = (e0 & 3) * 8;
    int r1 = e1 >> 2, c1 = (e1 & 3) * 8;

    int arow = lane & 15;
    int acolh = (lane >> 4) * 8;
    int brow = (lane & 7) + ((lane >> 4) & 1) * 8;
    int bcolh = ((lane >> 3) & 1) * 8;

    for (int kt = 0; kt < KD; kt += 32) {
        __syncthreads();
        {
            const __nv_bfloat16* a_h = Ah + (size_t)m0 * KD + kt;
            const __nv_bfloat16* a_l = Al + (size_t)m0 * KD + kt;
            const __nv_bfloat16* b_h = Bh + (size_t)n0 * KD + kt;
            const __nv_bfloat16* b_l = Bl + (size_t)n0 * KD + kt;
            *(uint4*)&sA[0][r0 * SSTR + c0] = *(const uint4*)(a_h + (size_t)r0 * KD + c0);
            *(uint4*)&sA[0][r1 * SSTR + c1] = *(const uint4*)(a_h + (size_t)r1 * KD + c1);
            *(uint4*)&sA[1][r0 * SSTR + c0] = *(const uint4*)(a_l + (size_t)r0 * KD + c0);
            *(uint4*)&sA[1][r1 * SSTR + c1] = *(const uint4*)(a_l + (size_t)r1 * KD + c1);
            *(uint4*)&sB[0][r0 * SSTR + c0] = *(const uint4*)(b_h + (size_t)r0 * KD + c0);
            *(uint4*)&sB[0][r1 * SSTR + c1] = *(const uint4*)(b_h + (size_t)r1 * KD + c1);
            *(uint4*)&sB[1][r0 * SSTR + c0] = *(const uint4*)(b_l + (size_t)r0 * KD + c0);
            *(uint4*)&sB[1][r1 * SSTR + c1] = *(const uint4*)(b_l + (size_t)r1 * KD + c1);
        }
        __syncthreads();

#pragma unroll
        for (int ks = 0; ks < 32; ks += 16) {
            uint32_t ahf[4][4], alf[4][4];
#pragma unroll
            for (int mt = 0; mt < 4; mt++) {
                int r = wm * 64 + mt * 16 + arow;
                uint32_t off = (uint32_t)(r * SSTR + ks + acolh) * 2;
                ldmx4(ahf[mt][0], ahf[mt][1], ahf[mt][2], ahf[mt][3], sAh_u + off);
                ldmx4(alf[mt][0], alf[mt][1], alf[mt][2], alf[mt][3], sAl_u + off);
            }
            uint32_t bhf[4][2], blf[4][2];
#pragma unroll
            for (int ntp = 0; ntp < 2; ntp++) {
                int nb = wn * 32 + ntp * 16;
                uint32_t off = (uint32_t)((nb + brow) * SSTR + ks + bcolh) * 2;
                ldmx4(bhf[2*ntp][0], bhf[2*ntp][1], bhf[2*ntp+1][0], bhf[2*ntp+1][1], sBh_u + off);
                ldmx4(blf[2*ntp][0], blf[2*ntp][1], blf[2*ntp+1][0], blf[2*ntp+1][1], sBl_u + off);
            }
#pragma unroll
            for (int mt = 0; mt < 4; mt++)
#pragma unroll
                for (int nt = 0; nt < 4; nt++) {
                    mma_bf16(acc[mt][nt], ahf[mt], bhf[nt]);
                    mma_bf16(acc[mt][nt], ahf[mt], blf[nt]);
                    mma_bf16(acc[mt][nt], alf[mt], bhf[nt]);
                }
        }
    }

#pragma unroll
    for (int mt = 0; mt < 4; mt++) {
        int r = m0 + wm * 64 + mt * 16 + (lane >> 2);
#pragma unroll
        for (int nt = 0; nt < 4; nt++) {
            int c = n0 + wn * 32 + nt * 8 + (lane & 3) * 2;
            float2 o0, o1;
            o0.x = (acc[mt][nt][0] + bias[c]) * scale;
            o0.y = (acc[mt][nt][1] + bias[c + 1]) * scale;
            o1.x = (acc[mt][nt][2] + bias[c]) * scale;
            o1.y = (acc[mt][nt][3] + bias[c + 1]) * scale;
            if (Cf) {
                *(float2*)(Cf + (size_t)r * KD + c) = o0;
                *(float2*)(Cf + (size_t)(r + 8) * KD + c) = o1;
            }
            if (Chi) {
                __nv_bfloat162 h0, l0, h1, l1;
                split1(o0.x, h0.x, l0.x); split1(o0.y, h0.y, l0.y);
                split1(o1.x, h1.x, l1.x); split1(o1.y, h1.y, l1.y);
                *(__nv_bfloat162*)(Chi + (size_t)r * KD + c) = h0;
                *(__nv_bfloat162*)(Clo + (size_t)r * KD + c) = l0;
                *(__nv_bfloat162*)(Chi + (size_t)(r + 8) * KD + c) = h1;
                *(__nv_bfloat162*)(Clo + (size_t)(r + 8) * KD + c) = l1;
            }
        }
    }
}

// ---------------- HMMA scores: S = Q@K^T (masked) + per-tile stats -----------
// smem (halves): Qh 0, Ql 9216, Kh 18432, Kl 27648; floats sMax@73728B, sSum@75776B
#define SC_QH 0
#define SC_QL 9216
#define SC_KH 18432
#define SC_KL 27648
#define SC_SMEM 77824
#define SST 72

__global__ __launch_bounds__(256) void hscores(
    const __nv_bfloat16* __restrict__ qh, const __nv_bfloat16* __restrict__ ql,
    const __nv_bfloat16* __restrict__ kh, const __nv_bfloat16* __restrict__ kl,
    float* __restrict__ W)
{
    extern __shared__ __align__(16) char smraw[];
    __nv_bfloat16* S = (__nv_bfloat16*)smraw;
    float* sMax = (float*)(smraw + 73728);
    float* sSum = (float*)(smraw + 75776);
    uint32_t sb = smem_u32(smraw);

    int bh = blockIdx.z;
    int b = bh >> 4;
    int base = b * EMB + (bh & 15) * HD;
    int n0 = blockIdx.x * 128, m0 = blockIdx.y * 128;
    int tid = threadIdx.x;
    int warp = tid >> 5, lane = tid & 31;
    int wm = warp & 1, wn = warp >> 1;

    // copy Q/K tiles (128 rows x 64 halves each, 4 tiles)
#pragma unroll
    for (int l = 0; l < 4; l++) {
        int e = tid + 256 * l;
        int row = e >> 3, c8 = (e & 7) * 8;
        size_t qa = (size_t)(m0 + row) * (BSZ*EMB) + base + c8;
        size_t ka = (size_t)(n0 + row) * (BSZ*EMB) + base + c8;
        int so = row * SST + c8;
        *(uint4*)&S[SC_QH + so] = *(const uint4*)(qh + qa);
        *(uint4*)&S[SC_QL + so] = *(const uint4*)(ql + qa);
        *(uint4*)&S[SC_KH + so] = *(const uint4*)(kh + ka);
        *(uint4*)&S[SC_KL + so] = *(const uint4*)(kl + ka);
    }
    __syncthreads();

    float acc[4][4][4];
#pragma unroll
    for (int i = 0; i < 4; i++)
#pragma unroll
        for (int j = 0; j < 4; j++)
#pragma unroll
            for (int q = 0; q < 4; q++) acc[i][j][q] = 0.f;

    int arow = lane & 15;
    int acolh = (lane >> 4) * 8;
    int brow = (lane & 7) + ((lane >> 4) & 1) * 8;
    int bcolh = ((lane >> 3) & 1) * 8;

#pragma unroll
    for (int ks = 0; ks < 64; ks += 16) {
        uint32_t qhf[4][4], qlf[4][4];
#pragma unroll
        for (int mt = 0; mt < 4; mt++) {
            int r = wm * 64 + mt * 16 + arow;
            uint32_t off = sb + (uint32_t)(r * SST + ks + acolh) * 2;
            ldmx4(qhf[mt][0], qhf[mt][1], qhf[mt][2], qhf[mt][3], off + SC_QH * 2);
            ldmx4(qlf[mt][0], qlf[mt][1], qlf[mt][2], qlf[mt][3], off + SC_QL * 2);
        }
        uint32_t khf[4][2], klf[4][2];
#pragma unroll
        for (int ntp = 0; ntp < 2; ntp++) {
            int nb = wn * 32 + ntp * 16;
            uint32_t off = sb + (uint32_t)((nb + brow) * SST + ks + bcolh) * 2;
            ldmx4(khf[2*ntp][0], khf[2*ntp][1], khf[2*ntp+1][0], khf[2*ntp+1][1], off + SC_KH * 2);
            ldmx4(klf[2*ntp][0], klf[2*ntp][1], klf[2*ntp+1][0], klf[2*ntp+1][1], off + SC_KL * 2);
        }
#pragma unroll
        for (int mt = 0; mt < 4; mt++)
#pragma unroll
            for (int nt = 0; nt < 4; nt++) {
                mma_bf16(acc[mt][nt], qhf[mt], khf[nt]);
                mma_bf16(acc[mt][nt], qhf[mt], klf[nt]);
                mma_bf16(acc[mt][nt], qlf[mt], khf[nt]);
            }
    }

    // epilogue: mask, write raw S, per-row tile stats
    int qr = lane >> 2, qc = (lane & 3) * 2;
    unsigned char mk[4][2];
#pragma unroll
    for (int nt = 0; nt < 4; nt++) {
        int c = n0 + wn * 32 + nt * 8 + qc;
        mk[nt][0] = g_mask[b * TGT + c];
        mk[nt][1] = g_mask[b * TGT + c + 1];
    }
    long long wbase = (long long)bh * TGT * TGT;

#pragma unroll
    for (int mt = 0; mt < 4; mt++) {
        int rl = wm * 64 + mt * 16 + qr;   // local row (0..127)
        int rg = m0 + rl;
        float v0[8], v1[8];
#pragma unroll
        for (int nt = 0; nt < 4; nt++) {
            float x;
            x = acc[mt][nt][0]; if (mk[nt][0]) x = NEGMAX; v0[2*nt]   = x;
            x = acc[mt][nt][1]; if (mk[nt][1]) x = NEGMAX; v0[2*nt+1] = x;
            x = acc[mt][nt][2]; if (mk[nt][0]) x = NEGMAX; v1[2*nt]   = x;
            x = acc[mt][nt][3]; if (mk[nt][1]) x = NEGMAX; v1[2*nt+1] = x;
        }
#pragma unroll
        for (int nt = 0; nt < 4; nt++) {
            int c = n0 + wn * 32 + nt * 8 + qc;
            *(float2*)(W + wbase + (long long)rg * TGT + c) = make_float2(v0[2*nt], v0[2*nt+1]);
            *(float2*)(W + wbase + (long long)(rg + 8) * TGT + c) = make_float2(v1[2*nt], v1[2*nt+1]);
        }
        float mx0 = v0[0], mx1 = v1[0];
#pragma unroll
        for (int j = 1; j < 8; j++) { mx0 = fmaxf(mx0, v0[j]); mx1 = fmaxf(mx1, v1[j]); }
#pragma unroll
        for (int o = 1; o <= 2; o <<= 1) {
            mx0 = fmaxf(mx0, __shfl_xor_sync(0xffffffffu, mx0, o));
            mx1 = fmaxf(mx1, __shfl_xor_sync(0xffffffffu, mx1, o));
        }
        float se0 = 0.f, se1 = 0.f;
#pragma unroll
        for (int j = 0; j < 8; j++) { se0 += __expf(v0[j] - mx0); se1 += __expf(v1[j] - mx1); }
#pragma unroll
        for (int o = 1; o <= 2; o <<= 1) {
            se0 += __shfl_xor_sync(0xffffffffu, se0, o);
            se1 += __shfl_xor_sync(0xffffffffu, se1, o);
        }
        if ((lane & 3) == 0) {
            sMax[rl * 4 + wn] = mx0;       sSum[rl * 4 + wn] = se0;
            sMax[(rl + 8) * 4 + wn] = mx1; sSum[(rl + 8) * 4 + wn] = se1;
        }
    }
    __syncthreads();
    if (tid < 128) {
        float m0v = sMax[tid*4], m1v = sMax[tid*4+1], m2v = sMax[tid*4+2], m3v = sMax[tid*4+3];
        float gm = fmaxf(fmaxf(m0v, m1v), fmaxf(m2v, m3v));
        float s = sSum[tid*4] * __expf(m0v - gm) + sSum[tid*4+1] * __expf(m1v - gm)
                + sSum[tid*4+2] * __expf(m2v - gm) + sSum[tid*4+3] * __expf(m3v - gm);
        int sidx = (bh * NTILE + blockIdx.x) * TGT + m0 + tid;
        g_tmax[sidx] = gm;
        g_tsum[sidx] = s;
    }
}

// ------- combine per-tile stats into per-row (max, 1/sum) ---------------------
__global__ __launch_bounds__(256) void stats_combine()
{
    int idx = blockIdx.x * 256 + threadIdx.x;
    int bh = idx >> 11, row = idx & 2047;
    float gm = -INFINITY;
#pragma unroll
    for (int t = 0; t < NTILE; t++)
        gm = fmaxf(gm, g_tmax[(bh * NTILE + t) * TGT + row]);
    float s = 0.f;
#pragma unroll
    for (int t = 0; t < NTILE; t++)
        s += g_tsum[(bh * NTILE + t) * TGT + row] * __expf(g_tmax[(bh * NTILE + t) * TGT + row] - gm);
    g_rmax[idx] = gm;
    g_rinv[idx] = 1.0f / s;
}

// ---------------- HMMA AV: normalize S in place (-> P output) + ctx = P@V ----
// smem halves: Ph 0, Pl 9216, Vh 18432, Vl 23040; total 55296 B
#define AV_PH 0
#define AV_PL 9216
#define AV_VH 18432
#define AV_VL 23040
#define AV_SMEM 55296

__global__ __launch_bounds__(256) void hav(
    float* __restrict__ W, const float* __restrict__ v,
    __nv_bfloat16* __restrict__ ch, __nv_bfloat16* __restrict__ cl)
{
    extern __shared__ __align__(16) char smraw[];
    __nv_bfloat16* S = (__nv_bfloat16*)smraw;
    uint32_t sb = smem_u32(smraw);

    int bh = blockIdx.y;
    int b = bh >> 4;
    int base = b * EMB + (bh & 15) * HD;
    int m0 = blockIdx.x * 128;
    float* P = W + (long long)bh * TGT * TGT;
    int tid = threadIdx.x;
    int warp = tid >> 5, lane = tid & 31;
    int wm = warp & 3, wn = warp >> 2;

    int myrow = tid >> 1;
    int mycol0 = (tid & 1) * 32;
    float rm = g_rmax[bh * TGT + m0 + myrow];
    float ri = g_rinv[bh * TGT + m0 + myrow];

    int arow = lane & 15;
    int acolh = (lane >> 4) * 8;
    int brow = (lane & 7) + ((lane >> 4) & 1) * 8;
    int bcolh = ((lane >> 3) & 1) * 8;
    int vkey = tid >> 2, vd0 = (tid & 3) * 16;

    float acc[2][4][4];
#pragma unroll
    for (int i = 0; i < 2; i++)
#pragma unroll
        for (int j = 0; j < 4; j++)
#pragma unroll
            for (int q = 0; q < 4; q++) acc[i][j][q] = 0.f;

    for (int kt = 0; kt < TGT; kt += 64) {
        // P: normalize 128x64 chunk, write gmem, split into smem
        float* srow = P + (long long)(m0 + myrow) * TGT + kt + mycol0;
#pragma unroll
        for (int l = 0; l < 8; l++) {
            float4 s4 = *(float4*)(srow + l * 4);
            float4 p4;
            p4.x = __expf(s4.x - rm) * ri;
            p4.y = __expf(s4.y - rm) * ri;
            p4.z = __expf(s4.z - rm) * ri;
            p4.w = __expf(s4.w - rm) * ri;
            *(float4*)(srow + l * 4) = p4;
            int c = mycol0 + l * 4;
            __nv_bfloat162 h0, l0, h1, l1;
            split1(p4.x, h0.x, l0.x); split1(p4.y, h0.y, l0.y);
            split1(p4.z, h1.x, l1.x); split1(p4.w, h1.y, l1.y);
            int so = myrow * SST + c;
            *(__nv_bfloat162*)&S[AV_PH + so] = h0;
            *(__nv_bfloat162*)&S[AV_PH + so + 2] = h1;
            *(__nv_bfloat162*)&S[AV_PL + so] = l0;
            *(__nv_bfloat162*)&S[AV_PL + so + 2] = l1;
        }
        // V: 64 keys x 64 d, split + transpose into smem [d][key]
        const float* vp = v + (size_t)(kt + vkey) * (BSZ*EMB) + base + vd0;
#pragma unroll
        for (int j = 0; j < 4; j++) {
            float4 v4 = *(const float4*)(vp + j * 4);
            float vv[4] = {v4.x, v4.y, v4.z, v4.w};
#pragma unroll
            for (int m = 0; m < 4; m++) {
                int d = vd0 + j * 4 + m;
                __nv_bfloat16 h, l;
                split1(vv[m], h, l);
                S[AV_VH + d * SST + vkey] = h;
                S[AV_VL + d * SST + vkey] = l;
            }
        }
        __syncthreads();

#pragma unroll
        for (int ks = 0; ks < 64; ks += 16) {
            uint32_t pah[2][4], pal[2][4];
#pragma unroll
            for (int mt = 0; mt < 2; mt++) {
                int r = wm * 32 + mt * 16 + arow;
                uint32_t off = sb + (uint32_t)(r * SST + ks + acolh) * 2;
                ldmx4(pah[mt][0], pah[mt][1], pah[mt][2], pah[mt][3], off + AV_PH * 2);
                ldmx4(pal[mt][0], pal[mt][1], pal[mt][2], pal[mt][3], off + AV_PL * 2);
            }
            uint32_t bvh[4][2], bvl[4][2];
#pragma unroll
            for (int ntp = 0; ntp < 2; ntp++) {
                int nb = wn * 32 + ntp * 16;
                uint32_t off = sb + (uint32_t)((nb + brow) * SST + ks + bcolh) * 2;
                ldmx4(bvh[2*ntp][0], bvh[2*ntp][1], bvh[2*ntp+1][0], bvh[2*ntp+1][1], off + AV_VH * 2);
                ldmx4(bvl[2*ntp][0], bvl[2*ntp][1], bvl[2*ntp+1][0], bvl[2*ntp+1][1], off + AV_VL * 2);
            }
#pragma unroll
            for (int mt = 0; mt < 2; mt++)
#pragma unroll
                for (int nt = 0; nt < 4; nt++) {
                    mma_bf16(acc[mt][nt], pah[mt], bvh[nt]);
                    mma_bf16(acc[mt][nt], pah[mt], bvl[nt]);
                    mma_bf16(acc[mt][nt], pal[mt], bvh[nt]);
                }
        }
        __syncthreads();
    }

    // epilogue: write ctx split-bf16 in (t*BSZ+b, h*64+d) layout
    int qr = lane >> 2, qc = (lane & 3) * 2;
#pragma unroll
    for (int mt = 0; mt < 2; mt++) {
        int t = m0 + wm * 32 + mt * 16 + qr;
#pragma unroll
        for (int nt = 0; nt < 4; nt++) {
            int d = wn * 32 + nt * 8 + qc;
            size_t i0 = (size_t)(t * BSZ + b) * EMB + (bh & 15) * HD + d;
            size_t i1 = (size_t)((t + 8) * BSZ + b) * EMB + (bh & 15) * HD + d;
            __nv_bfloat162 h0, l0, h1, l1;
            split1(acc[mt][nt][0], h0.x, l0.x); split1(acc[mt][nt][1], h0.y, l0.y);
            split1(acc[mt][nt][2], h1.x, l1.x); split1(acc[mt][nt][3], h1.y, l1.y);
            *(__nv_bfloat162*)(ch + i0) = h0;
            *(__nv_bfloat162*)(cl + i0) = l0;
            *(__nv_bfloat162*)(ch + i1) = h1;
            *(__nv_bfloat162*)(cl + i1) = l1;
        }
    }
}

// ---------------- mask dtype auto-detect + normalize -------------------------
__global__ void mask_prep(const void* m) {
    __shared__ int mode;
    int tid = threadIdx.x;
    if (tid == 0) {
        const int* mi = (const int*)m;
        int ok_i = 1;
        for (int i = 0; i < 1024; i++) { int v = mi[i]; if (v != 0 && v != 1) { ok_i = 0; break; } }
        if (ok_i) mode = 0;
        else {
            const float* mf = (const float*)m;
            int ok_f = 1;
            for (int i = 0; i < 1024; i++) { float v = mf[i]; if (v != 0.0f && v != 1.0f) { ok_f = 0; break; } }
            mode = ok_f ? 1 : 2;
        }
    }
    __syncthreads();
    int md = mode;
    for (int i = tid; i < BSZ*TGT; i += blockDim.x) {
        bool b;
        if (md == 0)      b = ((const int*)m)[i] != 0;
        else if (md == 1) b = ((const float*)m)[i] != 0.0f;
        else              b = ((const unsigned char*)m)[i] != 0;
        g_mask[i] = b ? 1 : 0;
    }
}

// ---------------- launch -----------------------------------------------------
extern "C" void kernel_launch(void* const* d_in, const int* in_sizes, int n_in,
                              void* d_out, int out_size)
{
    const float* query = (const float*)d_in[0];
    const void*  maskp = d_in[1];
    const float* qw = (const float*)d_in[2];
    const float* qb = (const float*)d_in[3];
    const float* kw = (const float*)d_in[4];
    const float* kb = (const float*)d_in[5];
    const float* vw = (const float*)d_in[6];
    const float* vb = (const float*)d_in[7];
    const float* ow = (const float*)d_in[8];
    const float* ob = (const float*)d_in[9];
    float* out = (float*)d_out;

    float *pv, *pwf;
    cudaGetSymbolAddress((void**)&pv,  g_v);
    cudaGetSymbolAddress((void**)&pwf, g_wfallback);

    __nv_bfloat16 *ah, *al, *ch, *cl, *qh_, *ql_, *kh_, *kl_;
    __nv_bfloat16 *qwh, *qwl, *kwh, *kwl, *vwh, *vwl, *owh, *owl;
    cudaGetSymbolAddress((void**)&ah,  g_ah);  cudaGetSymbolAddress((void**)&al,  g_al);
    cudaGetSymbolAddress((void**)&ch,  g_ch);  cudaGetSymbolAddress((void**)&cl,  g_cl);
    cudaGetSymbolAddress((void**)&qh_, g_qh);  cudaGetSymbolAddress((void**)&ql_, g_ql);
    cudaGetSymbolAddress((void**)&kh_, g_kh);  cudaGetSymbolAddress((void**)&kl_, g_kl);
    cudaGetSymbolAddress((void**)&qwh, g_qwh); cudaGetSymbolAddress((void**)&qwl, g_qwl);
    cudaGetSymbolAddress((void**)&kwh, g_kwh); cudaGetSymbolAddress((void**)&kwl, g_kwl);
    cudaGetSymbolAddress((void**)&vwh, g_vwh); cudaGetSymbolAddress((void**)&vwl, g_vwl);
    cudaGetSymbolAddress((void**)&owh, g_owh); cudaGetSymbolAddress((void**)&owl, g_owl);

    float* W = ((long long)out_size >= (long long)ATTN_N + W_ELEMS) ? (out + ATTN_N) : pwf;

    cudaFuncSetAttribute(hscores, cudaFuncAttributeMaxDynamicSharedMemorySize, SC_SMEM);
    cudaFuncSetAttribute(hav, cudaFuncAttributeMaxDynamicSharedMemorySize, AV_SMEM);

    mask_prep<<<1, 256>>>(maskp);

    split_kernel<<<ROWS*EMB/1024, 256>>>(query, ah, al, ROWS*EMB);
    split_kernel<<<EMB*EMB/1024, 256>>>(qw, qwh, qwl, EMB*EMB);
    split_kernel<<<EMB*EMB/1024, 256>>>(kw, kwh, kwl, EMB*EMB);
    split_kernel<<<EMB*EMB/1024, 256>>>(vw, vwh, vwl, EMB*EMB);
    split_kernel<<<EMB*EMB/1024, 256>>>(ow, owh, owl, EMB*EMB);

    dim3 gproj(EMB / 128, ROWS / 128);         // (8, 32)
    hgemm<<<gproj, 256>>>(ah, al, qwh, qwl, qb, nullptr, qh_, ql_, 0.125f);
    hgemm<<<gproj, 256>>>(ah, al, kwh, kwl, kb, nullptr, kh_, kl_, 1.0f);
    hgemm<<<gproj, 256>>>(ah, al, vwh, vwl, vb, pv, nullptr, nullptr, 1.0f);

    hscores<<<dim3(TGT / 128, TGT / 128, BH), 256, SC_SMEM>>>(qh_, ql_, kh_, kl_, W);

    stats_combine<<<BH * TGT / 256, 256>>>();

    hav<<<dim3(TGT / 128, BH), 256, AV_SMEM>>>(W, pv, ch, cl);

    hgemm<<<gproj, 256>>>(ch, cl, owh, owl, ob, out, nullptr, nullptr, 1.0f);
}

// round 9
// speedup vs baseline: 2.2627x; 1.4826x over previous
#include <cuda_runtime.h>
#include <cuda_bf16.h>
#include <math.h>
#include <stdint.h>

#define TGT 2048
#define BSZ 2
#define EMB 1024
#define NH 16
#define HD 64
#define ROWS (TGT*BSZ)              // 4096
#define BH (BSZ*NH)                 // 32
#define ATTN_N (ROWS*EMB)           // 4194304
#define W_ELEMS (134217728LL)       // 32*2048*2048
#define NEGMAX (-3.4028234663852886e38f)
#define NTILE 16                    // 2048/128 key tiles
#define KD 1024

// ---------------- scratch (static device memory; no allocations) -------------
__device__ float g_wfallback[134217728];
__device__ unsigned char g_mask[BSZ*TGT];
__device__ float g_tmax[BH*NTILE*TGT];
__device__ float g_tsum[BH*NTILE*TGT];
__device__ float g_rmax[BH*TGT];
__device__ float g_rinv[BH*TGT];

// split-bf16 operands
__device__ __nv_bfloat16 g_ah[ROWS*EMB], g_al[ROWS*EMB];          // input query hi/lo
__device__ __nv_bfloat16 g_ch[ROWS*EMB], g_cl[ROWS*EMB];          // ctx hi/lo
__device__ __nv_bfloat16 g_qh[ROWS*EMB], g_ql[ROWS*EMB];          // projected q hi/lo
__device__ __nv_bfloat16 g_kh[ROWS*EMB], g_kl[ROWS*EMB];          // projected k hi/lo
__device__ __nv_bfloat16 g_vh[ROWS*EMB], g_vl[ROWS*EMB];          // projected v hi/lo
__device__ __nv_bfloat16 g_qwh[EMB*EMB], g_qwl[EMB*EMB];
__device__ __nv_bfloat16 g_kwh[EMB*EMB], g_kwl[EMB*EMB];
__device__ __nv_bfloat16 g_vwh[EMB*EMB], g_vwl[EMB*EMB];
__device__ __nv_bfloat16 g_owh[EMB*EMB], g_owl[EMB*EMB];

// ---------------- helpers ----------------------------------------------------
__device__ __forceinline__ uint32_t smem_u32(const void* p) {
    uint32_t a;
    asm("{ .reg .u64 t; cvta.to.shared.u64 t, %1; cvt.u32.u64 %0, t; }" : "=r"(a) : "l"(p));
    return a;
}
__device__ __forceinline__ void ldmx4(uint32_t& r0, uint32_t& r1, uint32_t& r2, uint32_t& r3, uint32_t addr) {
    asm volatile("ldmatrix.sync.aligned.m8n8.x4.shared.b16 {%0,%1,%2,%3}, [%4];"
                 : "=r"(r0), "=r"(r1), "=r"(r2), "=r"(r3) : "r"(addr));
}
__device__ __forceinline__ void ldmx4t(uint32_t& r0, uint32_t& r1, uint32_t& r2, uint32_t& r3, uint32_t addr) {
    asm volatile("ldmatrix.sync.aligned.m8n8.x4.trans.shared.b16 {%0,%1,%2,%3}, [%4];"
                 : "=r"(r0), "=r"(r1), "=r"(r2), "=r"(r3) : "r"(addr));
}
__device__ __forceinline__ void mma_bf16(float* d, const uint32_t* a, const uint32_t* b) {
    asm volatile("mma.sync.aligned.m16n8k16.row.col.f32.bf16.bf16.f32 "
                 "{%0,%1,%2,%3}, {%4,%5,%6,%7}, {%8,%9}, {%0,%1,%2,%3};"
                 : "+f"(d[0]), "+f"(d[1]), "+f"(d[2]), "+f"(d[3])
                 : "r"(a[0]), "r"(a[1]), "r"(a[2]), "r"(a[3]), "r"(b[0]), "r"(b[1]));
}
__device__ __forceinline__ void split1(float x, __nv_bfloat16& h, __nv_bfloat16& l) {
    h = __float2bfloat16_rn(x);
    l = __float2bfloat16_rn(x - __bfloat162float(h));
}
__device__ __forceinline__ void split2(float x, float y, uint32_t& hi, uint32_t& lo) {
    __nv_bfloat162 h, l;
    split1(x, h.x, l.x);
    split1(y, h.y, l.y);
    hi = *(uint32_t*)&h;
    lo = *(uint32_t*)&l;
}

// ---------------- fp32 -> (hi, lo) bf16 split --------------------------------
__global__ __launch_bounds__(256) void split_kernel(const float* __restrict__ in,
                                                    __nv_bfloat16* __restrict__ hi,
                                                    __nv_bfloat16* __restrict__ lo, int n)
{
    int i = (blockIdx.x * 256 + threadIdx.x) * 4;
    if (i >= n) return;
    float4 x = *(const float4*)(in + i);
    __nv_bfloat162 hh0, hh1, ll0, ll1;
    split1(x.x, hh0.x, ll0.x); split1(x.y, hh0.y, ll0.y);
    split1(x.z, hh1.x, ll1.x); split1(x.w, hh1.y, ll1.y);
    *(__nv_bfloat162*)(hi + i) = hh0; *(__nv_bfloat162*)(hi + i + 2) = hh1;
    *(__nv_bfloat162*)(lo + i) = ll0; *(__nv_bfloat162*)(lo + i + 2) = ll1;
}

// ---------------- split-bf16 HMMA NT GEMM ------------------------------------
#define SSTR 40

__global__ __launch_bounds__(256, 2) void hgemm(
    const __nv_bfloat16* __restrict__ Ah, const __nv_bfloat16* __restrict__ Al,
    const __nv_bfloat16* __restrict__ Bh, const __nv_bfloat16* __restrict__ Bl,
    const float* __restrict__ bias, float* __restrict__ Cf,
    __nv_bfloat16* __restrict__ Chi, __nv_bfloat16* __restrict__ Clo, float scale)
{
    __shared__ __align__(16) __nv_bfloat16 sA[2][128 * SSTR];
    __shared__ __align__(16) __nv_bfloat16 sB[2][128 * SSTR];

    int tid = threadIdx.x;
    int warp = tid >> 5, lane = tid & 31;
    int wm = warp & 1, wn = warp >> 1;
    int m0 = blockIdx.y * 128, n0 = blockIdx.x * 128;

    uint32_t sAh_u = smem_u32(sA[0]), sAl_u = smem_u32(sA[1]);
    uint32_t sBh_u = smem_u32(sB[0]), sBl_u = smem_u32(sB[1]);

    float acc[4][4][4];
#pragma unroll
    for (int i = 0; i < 4; i++)
#pragma unroll
        for (int j = 0; j < 4; j++)
#pragma unroll
            for (int q = 0; q < 4; q++) acc[i][j][q] = 0.f;

    int e0 = tid, e1 = tid + 256;
    int r0 = e0 >> 2, c0 = (e0 & 3) * 8;
    int r1 = e1 >> 2, c1 = (e1 & 3) * 8;

    int arow = lane & 15;
    int acolh = (lane >> 4) * 8;
    int brow = (lane & 7) + ((lane >> 4) & 1) * 8;
    int bcolh = ((lane >> 3) & 1) * 8;

    for (int kt = 0; kt < KD; kt += 32) {
        __syncthreads();
        {
            const __nv_bfloat16* a_h = Ah + (size_t)m0 * KD + kt;
            const __nv_bfloat16* a_l = Al + (size_t)m0 * KD + kt;
            const __nv_bfloat16* b_h = Bh + (size_t)n0 * KD + kt;
            const __nv_bfloat16* b_l = Bl + (size_t)n0 * KD + kt;
            *(uint4*)&sA[0][r0 * SSTR + c0] = *(const uint4*)(a_h + (size_t)r0 * KD + c0);
            *(uint4*)&sA[0][r1 * SSTR + c1] = *(const uint4*)(a_h + (size_t)r1 * KD + c1);
            *(uint4*)&sA[1][r0 * SSTR + c0] = *(const uint4*)(a_l + (size_t)r0 * KD + c0);
            *(uint4*)&sA[1][r1 * SSTR + c1] = *(const uint4*)(a_l + (size_t)r1 * KD + c1);
            *(uint4*)&sB[0][r0 * SSTR + c0] = *(const uint4*)(b_h + (size_t)r0 * KD + c0);
            *(uint4*)&sB[0][r1 * SSTR + c1] = *(const uint4*)(b_h + (size_t)r1 * KD + c1);
            *(uint4*)&sB[1][r0 * SSTR + c0] = *(const uint4*)(b_l + (size_t)r0 * KD + c0);
            *(uint4*)&sB[1][r1 * SSTR + c1] = *(const uint4*)(b_l + (size_t)r1 * KD + c1);
        }
        __syncthreads();

#pragma unroll
        for (int ks = 0; ks < 32; ks += 16) {
            uint32_t ahf[4][4], alf[4][4];
#pragma unroll
            for (int mt = 0; mt < 4; mt++) {
                int r = wm * 64 + mt * 16 + arow;
                uint32_t off = (uint32_t)(r * SSTR + ks + acolh) * 2;
                ldmx4(ahf[mt][0], ahf[mt][1], ahf[mt][2], ahf[mt][3], sAh_u + off);
                ldmx4(alf[mt][0], alf[mt][1], alf[mt][2], alf[mt][3], sAl_u + off);
            }
            uint32_t bhf[4][2], blf[4][2];
#pragma unroll
            for (int ntp = 0; ntp < 2; ntp++) {
                int nb = wn * 32 + ntp * 16;
                uint32_t off = (uint32_t)((nb + brow) * SSTR + ks + bcolh) * 2;
                ldmx4(bhf[2*ntp][0], bhf[2*ntp][1], bhf[2*ntp+1][0], bhf[2*ntp+1][1], sBh_u + off);
                ldmx4(blf[2*ntp][0], blf[2*ntp][1], blf[2*ntp+1][0], blf[2*ntp+1][1], sBl_u + off);
            }
#pragma unroll
            for (int mt = 0; mt < 4; mt++)
#pragma unroll
                for (int nt = 0; nt < 4; nt++) {
                    mma_bf16(acc[mt][nt], ahf[mt], bhf[nt]);
                    mma_bf16(acc[mt][nt], ahf[mt], blf[nt]);
                    mma_bf16(acc[mt][nt], alf[mt], bhf[nt]);
                }
        }
    }

#pragma unroll
    for (int mt = 0; mt < 4; mt++) {
        int r = m0 + wm * 64 + mt * 16 + (lane >> 2);
#pragma unroll
        for (int nt = 0; nt < 4; nt++) {
            int c = n0 + wn * 32 + nt * 8 + (lane & 3) * 2;
            float2 o0, o1;
            o0.x = (acc[mt][nt][0] + bias[c]) * scale;
            o0.y = (acc[mt][nt][1] + bias[c + 1]) * scale;
            o1.x = (acc[mt][nt][2] + bias[c]) * scale;
            o1.y = (acc[mt][nt][3] + bias[c + 1]) * scale;
            if (Cf) {
                *(float2*)(Cf + (size_t)r * KD + c) = o0;
                *(float2*)(Cf + (size_t)(r + 8) * KD + c) = o1;
            }
            if (Chi) {
                uint32_t h0, l0, h1, l1;
                split2(o0.x, o0.y, h0, l0);
                split2(o1.x, o1.y, h1, l1);
                *(uint32_t*)(Chi + (size_t)r * KD + c) = h0;
                *(uint32_t*)(Clo + (size_t)r * KD + c) = l0;
                *(uint32_t*)(Chi + (size_t)(r + 8) * KD + c) = h1;
                *(uint32_t*)(Clo + (size_t)(r + 8) * KD + c) = l1;
            }
        }
    }
}

// ---------------- HMMA scores: S = Q@K^T (masked) + per-tile stats -----------
#define SC_QH 0
#define SC_QL 9216
#define SC_KH 18432
#define SC_KL 27648
#define SC_SMEM 77824
#define SST 72

__global__ __launch_bounds__(256) void hscores(
    const __nv_bfloat16* __restrict__ qh, const __nv_bfloat16* __restrict__ ql,
    const __nv_bfloat16* __restrict__ kh, const __nv_bfloat16* __restrict__ kl,
    float* __restrict__ W)
{
    extern __shared__ __align__(16) char smraw[];
    __nv_bfloat16* S = (__nv_bfloat16*)smraw;
    float* sMax = (float*)(smraw + 73728);
    float* sSum = (float*)(smraw + 75776);
    uint32_t sb = smem_u32(smraw);

    int bh = blockIdx.z;
    int b = bh >> 4;
    int base = b * EMB + (bh & 15) * HD;
    int n0 = blockIdx.x * 128, m0 = blockIdx.y * 128;
    int tid = threadIdx.x;
    int warp = tid >> 5, lane = tid & 31;
    int wm = warp & 1, wn = warp >> 1;

#pragma unroll
    for (int l = 0; l < 4; l++) {
        int e = tid + 256 * l;
        int row = e >> 3, c8 = (e & 7) * 8;
        size_t qa = (size_t)(m0 + row) * (BSZ*EMB) + base + c8;
        size_t ka = (size_t)(n0 + row) * (BSZ*EMB) + base + c8;
        int so = row * SST + c8;
        *(uint4*)&S[SC_QH + so] = *(const uint4*)(qh + qa);
        *(uint4*)&S[SC_QL + so] = *(const uint4*)(ql + qa);
        *(uint4*)&S[SC_KH + so] = *(const uint4*)(kh + ka);
        *(uint4*)&S[SC_KL + so] = *(const uint4*)(kl + ka);
    }
    __syncthreads();

    float acc[4][4][4];
#pragma unroll
    for (int i = 0; i < 4; i++)
#pragma unroll
        for (int j = 0; j < 4; j++)
#pragma unroll
            for (int q = 0; q < 4; q++) acc[i][j][q] = 0.f;

    int arow = lane & 15;
    int acolh = (lane >> 4) * 8;
    int brow = (lane & 7) + ((lane >> 4) & 1) * 8;
    int bcolh = ((lane >> 3) & 1) * 8;

#pragma unroll
    for (int ks = 0; ks < 64; ks += 16) {
        uint32_t qhf[4][4], qlf[4][4];
#pragma unroll
        for (int mt = 0; mt < 4; mt++) {
            int r = wm * 64 + mt * 16 + arow;
            uint32_t off = sb + (uint32_t)(r * SST + ks + acolh) * 2;
            ldmx4(qhf[mt][0], qhf[mt][1], qhf[mt][2], qhf[mt][3], off + SC_QH * 2);
            ldmx4(qlf[mt][0], qlf[mt][1], qlf[mt][2], qlf[mt][3], off + SC_QL * 2);
        }
        uint32_t khf[4][2], klf[4][2];
#pragma unroll
        for (int ntp = 0; ntp < 2; ntp++) {
            int nb = wn * 32 + ntp * 16;
            uint32_t off = sb + (uint32_t)((nb + brow) * SST + ks + bcolh) * 2;
            ldmx4(khf[2*ntp][0], khf[2*ntp][1], khf[2*ntp+1][0], khf[2*ntp+1][1], off + SC_KH * 2);
            ldmx4(klf[2*ntp][0], klf[2*ntp][1], klf[2*ntp+1][0], klf[2*ntp+1][1], off + SC_KL * 2);
        }
#pragma unroll
        for (int mt = 0; mt < 4; mt++)
#pragma unroll
            for (int nt = 0; nt < 4; nt++) {
                mma_bf16(acc[mt][nt], qhf[mt], khf[nt]);
                mma_bf16(acc[mt][nt], qhf[mt], klf[nt]);
                mma_bf16(acc[mt][nt], qlf[mt], khf[nt]);
            }
    }

    int qr = lane >> 2, qc = (lane & 3) * 2;
    unsigned char mk[4][2];
#pragma unroll
    for (int nt = 0; nt < 4; nt++) {
        int c = n0 + wn * 32 + nt * 8 + qc;
        mk[nt][0] = g_mask[b * TGT + c];
        mk[nt][1] = g_mask[b * TGT + c + 1];
    }
    long long wbase = (long long)bh * TGT * TGT;

#pragma unroll
    for (int mt = 0; mt < 4; mt++) {
        int rl = wm * 64 + mt * 16 + qr;
        int rg = m0 + rl;
        float v0[8], v1[8];
#pragma unroll
        for (int nt = 0; nt < 4; nt++) {
            float x;
            x = acc[mt][nt][0]; if (mk[nt][0]) x = NEGMAX; v0[2*nt]   = x;
            x = acc[mt][nt][1]; if (mk[nt][1]) x = NEGMAX; v0[2*nt+1] = x;
            x = acc[mt][nt][2]; if (mk[nt][0]) x = NEGMAX; v1[2*nt]   = x;
            x = acc[mt][nt][3]; if (mk[nt][1]) x = NEGMAX; v1[2*nt+1] = x;
        }
#pragma unroll
        for (int nt = 0; nt < 4; nt++) {
            int c = n0 + wn * 32 + nt * 8 + qc;
            *(float2*)(W + wbase + (long long)rg * TGT + c) = make_float2(v0[2*nt], v0[2*nt+1]);
            *(float2*)(W + wbase + (long long)(rg + 8) * TGT + c) = make_float2(v1[2*nt], v1[2*nt+1]);
        }
        float mx0 = v0[0], mx1 = v1[0];
#pragma unroll
        for (int j = 1; j < 8; j++) { mx0 = fmaxf(mx0, v0[j]); mx1 = fmaxf(mx1, v1[j]); }
#pragma unroll
        for (int o = 1; o <= 2; o <<= 1) {
            mx0 = fmaxf(mx0, __shfl_xor_sync(0xffffffffu, mx0, o));
            mx1 = fmaxf(mx1, __shfl_xor_sync(0xffffffffu, mx1, o));
        }
        float se0 = 0.f, se1 = 0.f;
#pragma unroll
        for (int j = 0; j < 8; j++) { se0 += __expf(v0[j] - mx0); se1 += __expf(v1[j] - mx1); }
#pragma unroll
        for (int o = 1; o <= 2; o <<= 1) {
            se0 += __shfl_xor_sync(0xffffffffu, se0, o);
            se1 += __shfl_xor_sync(0xffffffffu, se1, o);
        }
        if ((lane & 3) == 0) {
            sMax[rl * 4 + wn] = mx0;       sSum[rl * 4 + wn] = se0;
            sMax[(rl + 8) * 4 + wn] = mx1; sSum[(rl + 8) * 4 + wn] = se1;
        }
    }
    __syncthreads();
    if (tid < 128) {
        float m0v = sMax[tid*4], m1v = sMax[tid*4+1], m2v = sMax[tid*4+2], m3v = sMax[tid*4+3];
        float gm = fmaxf(fmaxf(m0v, m1v), fmaxf(m2v, m3v));
        float s = sSum[tid*4] * __expf(m0v - gm) + sSum[tid*4+1] * __expf(m1v - gm)
                + sSum[tid*4+2] * __expf(m2v - gm) + sSum[tid*4+3] * __expf(m3v - gm);
        int sidx = (bh * NTILE + blockIdx.x) * TGT + m0 + tid;
        g_tmax[sidx] = gm;
        g_tsum[sidx] = s;
    }
}

// ------- combine per-tile stats into per-row (max, 1/sum) ---------------------
__global__ __launch_bounds__(256) void stats_combine()
{
    int idx = blockIdx.x * 256 + threadIdx.x;
    int bh = idx >> 11, row = idx & 2047;
    float gm = -INFINITY;
#pragma unroll
    for (int t = 0; t < NTILE; t++)
        gm = fmaxf(gm, g_tmax[(bh * NTILE + t) * TGT + row]);
    float s = 0.f;
#pragma unroll
    for (int t = 0; t < NTILE; t++)
        s += g_tsum[(bh * NTILE + t) * TGT + row] * __expf(g_tmax[(bh * NTILE + t) * TGT + row] - gm);
    g_rmax[idx] = gm;
    g_rinv[idx] = 1.0f / s;
}

// ---------------- hav2: P stays in registers; V via trans-ldmatrix -----------
// Warp tile: 16 query rows x 128 keys per k-tile; ctx 16 x 64.
#define VST 72

__global__ __launch_bounds__(256) void hav2(
    float* __restrict__ W,
    const __nv_bfloat16* __restrict__ vh, const __nv_bfloat16* __restrict__ vl,
    __nv_bfloat16* __restrict__ ch, __nv_bfloat16* __restrict__ cl)
{
    __shared__ __align__(16) __nv_bfloat16 sVh[128 * VST];
    __shared__ __align__(16) __nv_bfloat16 sVl[128 * VST];

    int bh = blockIdx.y, b = bh >> 4;
    int base = b * EMB + (bh & 15) * HD;
    int m0 = blockIdx.x * 128;
    float* P = W + (long long)bh * TGT * TGT;
    int tid = threadIdx.x, wq = tid >> 5, lane = tid & 31;
    int qr = lane >> 2, qc = (lane & 3) * 2;
    int row0 = m0 + wq * 16 + qr;           // query t index; row0+8 is second

    float rm0 = g_rmax[bh * TGT + row0],     ri0 = g_rinv[bh * TGT + row0];
    float rm1 = g_rmax[bh * TGT + row0 + 8], ri1 = g_rinv[bh * TGT + row0 + 8];

    uint32_t sVh_u = smem_u32(sVh), sVl_u = smem_u32(sVl);

    float ctx[8][4];
#pragma unroll
    for (int i = 0; i < 8; i++)
#pragma unroll
        for (int q = 0; q < 4; q++) ctx[i][q] = 0.f;

    // V copy geometry: 128 keys x 64 halves; 4 uint4 per thread per array
    int vrow[4], vcol[4];
#pragma unroll
    for (int l = 0; l < 4; l++) { int e = tid + 256 * l; vrow[l] = e >> 3; vcol[l] = (e & 7) * 8; }

    // trans-ldmatrix lane geometry (rows = keys, cols = d)
    int trow = (lane & 7) + ((lane >> 3) & 1) * 8;
    int tcol = ((lane >> 4) & 1) * 8;

    for (int kt = 0; kt < TGT; kt += 128) {
        __syncthreads();
#pragma unroll
        for (int l = 0; l < 4; l++) {
            size_t ga = (size_t)(kt + vrow[l]) * (BSZ*EMB) + base + vcol[l];
            *(uint4*)&sVh[vrow[l] * VST + vcol[l]] = *(const uint4*)(vh + ga);
            *(uint4*)&sVl[vrow[l] * VST + vcol[l]] = *(const uint4*)(vl + ga);
        }
        __syncthreads();

        // load raw S into fragment-position registers, normalize, write P back
        float2 p0[16], p1[16];
        long long pr0 = (long long)row0 * TGT + kt + qc;
        long long pr1 = (long long)(row0 + 8) * TGT + kt + qc;
#pragma unroll
        for (int nt = 0; nt < 16; nt++) {
            float2 s0 = *(float2*)(P + pr0 + nt * 8);
            float2 s1 = *(float2*)(P + pr1 + nt * 8);
            p0[nt].x = __expf(s0.x - rm0) * ri0;
            p0[nt].y = __expf(s0.y - rm0) * ri0;
            p1[nt].x = __expf(s1.x - rm1) * ri1;
            p1[nt].y = __expf(s1.y - rm1) * ri1;
        }
#pragma unroll
        for (int nt = 0; nt < 16; nt++) {
            *(float2*)(P + pr0 + nt * 8) = p0[nt];
            *(float2*)(P + pr1 + nt * 8) = p1[nt];
        }

        // mma: 8 k-chunks of 16 keys; A-frags packed straight from P registers
#pragma unroll
        for (int kc = 0; kc < 8; kc++) {
            uint32_t ah[4], al[4];
            split2(p0[2*kc].x,   p0[2*kc].y,   ah[0], al[0]);
            split2(p1[2*kc].x,   p1[2*kc].y,   ah[1], al[1]);
            split2(p0[2*kc+1].x, p0[2*kc+1].y, ah[2], al[2]);
            split2(p1[2*kc+1].x, p1[2*kc+1].y, ah[3], al[3]);
            int krow = kc * 16 + trow;
#pragma unroll
            for (int ng = 0; ng < 4; ng++) {
                uint32_t off = (uint32_t)(krow * VST + ng * 16 + tcol) * 2;
                uint32_t h0, h1, h2, h3, l0, l1, l2, l3;
                ldmx4t(h0, h1, h2, h3, sVh_u + off);
                ldmx4t(l0, l1, l2, l3, sVl_u + off);
                uint32_t bfh[2]  = {h0, h1}, bfh2[2] = {h2, h3};
                uint32_t bfl[2]  = {l0, l1}, bfl2[2] = {l2, l3};
                mma_bf16(ctx[ng*2], ah, bfh);
                mma_bf16(ctx[ng*2], ah, bfl);
                mma_bf16(ctx[ng*2], al, bfh);
                mma_bf16(ctx[ng*2+1], ah, bfh2);
                mma_bf16(ctx[ng*2+1], ah, bfl2);
                mma_bf16(ctx[ng*2+1], al, bfh2);
            }
        }
    }

    // epilogue: ctx split-bf16 in (t*BSZ+b, h*64+d) layout
#pragma unroll
    for (int nt2 = 0; nt2 < 8; nt2++) {
        int d = nt2 * 8 + qc;
        size_t i0 = (size_t)(row0 * BSZ + b) * EMB + (bh & 15) * HD + d;
        size_t i1 = (size_t)((row0 + 8) * BSZ + b) * EMB + (bh & 15) * HD + d;
        uint32_t h0, l0, h1, l1;
        split2(ctx[nt2][0], ctx[nt2][1], h0, l0);
        split2(ctx[nt2][2], ctx[nt2][3], h1, l1);
        *(uint32_t*)(ch + i0) = h0;
        *(uint32_t*)(cl + i0) = l0;
        *(uint32_t*)(ch + i1) = h1;
        *(uint32_t*)(cl + i1) = l1;
    }
}

// ---------------- mask dtype auto-detect + normalize -------------------------
__global__ void mask_prep(const void* m) {
    __shared__ int mode;
    int tid = threadIdx.x;
    if (tid == 0) {
        const int* mi = (const int*)m;
        int ok_i = 1;
        for (int i = 0; i < 1024; i++) { int v = mi[i]; if (v != 0 && v != 1) { ok_i = 0; break; } }
        if (ok_i) mode = 0;
        else {
            const float* mf = (const float*)m;
            int ok_f = 1;
            for (int i = 0; i < 1024; i++) { float v = mf[i]; if (v != 0.0f && v != 1.0f) { ok_f = 0; break; } }
            mode = ok_f ? 1 : 2;
        }
    }
    __syncthreads();
    int md = mode;
    for (int i = tid; i < BSZ*TGT; i += blockDim.x) {
        bool b;
        if (md == 0)      b = ((const int*)m)[i] != 0;
        else if (md == 1) b = ((const float*)m)[i] != 0.0f;
        else              b = ((const unsigned char*)m)[i] != 0;
        g_mask[i] = b ? 1 : 0;
    }
}

// ---------------- launch -----------------------------------------------------
extern "C" void kernel_launch(void* const* d_in, const int* in_sizes, int n_in,
                              void* d_out, int out_size)
{
    const float* query = (const float*)d_in[0];
    const void*  maskp = d_in[1];
    const float* qw = (const float*)d_in[2];
    const float* qb = (const float*)d_in[3];
    const float* kw = (const float*)d_in[4];
    const float* kb = (const float*)d_in[5];
    const float* vw = (const float*)d_in[6];
    const float* vb = (const float*)d_in[7];
    const float* ow = (const float*)d_in[8];
    const float* ob = (const float*)d_in[9];
    float* out = (float*)d_out;

    float* pwf;
    cudaGetSymbolAddress((void**)&pwf, g_wfallback);

    __nv_bfloat16 *ah, *al, *ch, *cl, *qh_, *ql_, *kh_, *kl_, *vh_, *vl_;
    __nv_bfloat16 *qwh, *qwl, *kwh, *kwl, *vwh, *vwl, *owh, *owl;
    cudaGetSymbolAddress((void**)&ah,  g_ah);  cudaGetSymbolAddress((void**)&al,  g_al);
    cudaGetSymbolAddress((void**)&ch,  g_ch);  cudaGetSymbolAddress((void**)&cl,  g_cl);
    cudaGetSymbolAddress((void**)&qh_, g_qh);  cudaGetSymbolAddress((void**)&ql_, g_ql);
    cudaGetSymbolAddress((void**)&kh_, g_kh);  cudaGetSymbolAddress((void**)&kl_, g_kl);
    cudaGetSymbolAddress((void**)&vh_, g_vh);  cudaGetSymbolAddress((void**)&vl_, g_vl);
    cudaGetSymbolAddress((void**)&qwh, g_qwh); cudaGetSymbolAddress((void**)&qwl, g_qwl);
    cudaGetSymbolAddress((void**)&kwh, g_kwh); cudaGetSymbolAddress((void**)&kwl, g_kwl);
    cudaGetSymbolAddress((void**)&vwh, g_vwh); cudaGetSymbolAddress((void**)&vwl, g_vwl);
    cudaGetSymbolAddress((void**)&owh, g_owh); cudaGetSymbolAddress((void**)&owl, g_owl);

    float* W = ((long long)out_size >= (long long)ATTN_N + W_ELEMS) ? (out + ATTN_N) : pwf;

    cudaFuncSetAttribute(hscores, cudaFuncAttributeMaxDynamicSharedMemorySize, SC_SMEM);

    mask_prep<<<1, 256>>>(maskp);

    split_kernel<<<ROWS*EMB/1024, 256>>>(query, ah, al, ROWS*EMB);
    split_kernel<<<EMB*EMB/1024, 256>>>(qw, qwh, qwl, EMB*EMB);
    split_kernel<<<EMB*EMB/1024, 256>>>(kw, kwh, kwl, EMB*EMB);
    split_kernel<<<EMB*EMB/1024, 256>>>(vw, vwh, vwl, EMB*EMB);
    split_kernel<<<EMB*EMB/1024, 256>>>(ow, owh, owl, EMB*EMB);

    dim3 gproj(EMB / 128, ROWS / 128);         // (8, 32)
    hgemm<<<gproj, 256>>>(ah, al, qwh, qwl, qb, nullptr, qh_, ql_, 0.125f);
    hgemm<<<gproj, 256>>>(ah, al, kwh, kwl, kb, nullptr, kh_, kl_, 1.0f);
    hgemm<<<gproj, 256>>>(ah, al, vwh, vwl, vb, nullptr, vh_, vl_, 1.0f);

    hscores<<<dim3(TGT / 128, TGT / 128, BH), 256, SC_SMEM>>>(qh_, ql_, kh_, kl_, W);

    stats_combine<<<BH * TGT / 256, 256>>>();

    hav2<<<dim3(TGT / 128, BH), 256>>>(W, vh_, vl_, ch, cl);

    hgemm<<<gproj, 256>>>(ch, cl, owh, owl, ob, out, nullptr, nullptr, 1.0f);
}